// round 1
// baseline (speedup 1.0000x reference)
#include <cuda_runtime.h>
#include <math.h>
#include <stdint.h>

#define T_LEN 1016
#define LT 16
#define HT 16

// ---------------- scratch (single static device buffer, carved by offsets) ---------
constexpr size_t OFF_Y     = 0;                                   // 32768*128
constexpr size_t OFF_CRAW  = OFF_Y     + (size_t)32768*128;       // 2048*T
constexpr size_t OFF_C1    = OFF_CRAW  + (size_t)2048*T_LEN;      // 2048*T
constexpr size_t OFF_CACTS = OFF_C1    + (size_t)2048*T_LEN;      // 2048*T
constexpr size_t OFF_WCT   = OFF_CACTS + (size_t)2048*T_LEN;      // 2048*2048
constexpr size_t OFF_WOT   = OFF_WCT   + (size_t)2048*2048;       // 256*256
constexpr size_t OFF_WET   = OFF_WOT   + (size_t)256*256;         // 256*256
constexpr size_t OFF_X0    = OFF_WET   + (size_t)256*256;         // 64*T
constexpr size_t OFF_X1    = OFF_X0    + (size_t)64*T_LEN;        // 64*T
constexpr size_t OFF_SKIP  = OFF_X1    + (size_t)64*T_LEN;        // 256*T
constexpr size_t OFF_H1    = OFF_SKIP  + (size_t)256*T_LEN;       // 256*T
constexpr size_t OFF_Q     = OFF_H1    + (size_t)256*T_LEN;       // 1024 (ints)
constexpr size_t SCRATCH_SZ = OFF_Q + 1024;

__device__ __align__(16) float g_scratch[SCRATCH_SZ];

// ---------------- mu-law encode + q output ----------------------------------------
__global__ void k_encode(const float* __restrict__ audio, float* __restrict__ q_out,
                         int write_q)
{
    int t = blockIdx.x * 256 + threadIdx.x;
    if (t >= T_LEN) return;
    float x = audio[t];
    float xc = fminf(1.0f, fmaxf(-1.0f, x));
    float s  = (xc > 0.0f) ? 1.0f : ((xc < 0.0f) ? -1.0f : 0.0f);
    float num = log1pf(__fmul_rn(255.0f, fabsf(xc)));
    float den = log1pf(255.0f);
    float m = __fdiv_rn(__fmul_rn(s, num), den);
    float v = __fadd_rn(__fmul_rn(__fmul_rn(__fadd_rn(m, 1.0f), 0.5f), 255.0f), 0.5f);
    v = fminf(255.0f, fmaxf(0.0f, v));
    int q = (int)v;
    ((int*)(g_scratch + OFF_Q))[t] = q;
    if (write_q) q_out[t] = (float)q;
}

// ---------------- embedding lookup -> x0 (64 x T) ----------------------------------
__global__ void k_embed(const float* __restrict__ embed)
{
    int idx = blockIdx.x * 256 + threadIdx.x;
    if (idx >= 64 * T_LEN) return;
    int t = idx % T_LEN, j = idx / T_LEN;
    int q = ((const int*)(g_scratch + OFF_Q))[t];
    g_scratch[OFF_X0 + (size_t)j * T_LEN + t] = embed[q * 64 + j];
}

// ---------------- transpose (R x C row-major -> C x R) -----------------------------
__global__ void k_transpose(const float* __restrict__ in, float* __restrict__ out,
                            int R, int C)
{
    __shared__ float tile[32][33];
    int c0 = blockIdx.x * 32, r0 = blockIdx.y * 32;
    int x = threadIdx.x, y = threadIdx.y;
#pragma unroll
    for (int i = 0; i < 32; i += 8)
        tile[y + i][x] = in[(size_t)(r0 + y + i) * C + c0 + x];
    __syncthreads();
#pragma unroll
    for (int i = 0; i < 32; i += 8)
        out[(size_t)(c0 + y + i) * R + r0 + x] = tile[x][y + i];
}

// ---------------- big GEMM: C[M,N] = A^T B, A (KxM k-major), B (KxN k-major) -------
__global__ __launch_bounds__(256)
void k_gemm(const float* __restrict__ A, const float* __restrict__ B,
            float* __restrict__ C, const float* __restrict__ bias,
            int M, int N, int K)
{
    __shared__ float As[16][128];
    __shared__ float Bs[16][128];
    int bm = blockIdx.x * 128;
    int bn = blockIdx.y * 128;
    int tid = threadIdx.x;
    int tx = tid & 15;        // n
    int ty = tid >> 4;        // m
    float acc[8][8];
#pragma unroll
    for (int i = 0; i < 8; i++)
#pragma unroll
        for (int j = 0; j < 8; j++) acc[i][j] = 0.0f;

    for (int k0 = 0; k0 < K; k0 += 16) {
#pragma unroll
        for (int i = 0; i < 2; i++) {
            int idx = (tid + i * 256) * 4;     // 0..2044
            int kr = idx >> 7;
            int mc = idx & 127;
            *(float4*)&As[kr][mc] =
                *(const float4*)&A[(size_t)(k0 + kr) * M + bm + mc];
            int col = bn + mc;
            float4 v = make_float4(0.f, 0.f, 0.f, 0.f);
            if (col < N)                        // N % 4 == 0, col % 4 == 0 -> safe
                v = *(const float4*)&B[(size_t)(k0 + kr) * N + col];
            *(float4*)&Bs[kr][mc] = v;
        }
        __syncthreads();
#pragma unroll
        for (int kk = 0; kk < 16; kk++) {
            float4 a0 = *(float4*)&As[kk][ty * 8];
            float4 a1 = *(float4*)&As[kk][ty * 8 + 4];
            float4 b0 = *(float4*)&Bs[kk][tx * 8];
            float4 b1 = *(float4*)&Bs[kk][tx * 8 + 4];
            float av[8] = {a0.x, a0.y, a0.z, a0.w, a1.x, a1.y, a1.z, a1.w};
            float bv[8] = {b0.x, b0.y, b0.z, b0.w, b1.x, b1.y, b1.z, b1.w};
#pragma unroll
            for (int i = 0; i < 8; i++)
#pragma unroll
                for (int j = 0; j < 8; j++) acc[i][j] += av[i] * bv[j];
        }
        __syncthreads();
    }
#pragma unroll
    for (int i = 0; i < 8; i++) {
        int row = bm + ty * 8 + i;
        float bb = bias ? bias[row] : 0.0f;
#pragma unroll
        for (int j = 0; j < 8; j += 4) {
            int col = bn + tx * 8 + j;
            if (col < N) {
                float4 v = make_float4(acc[i][j] + bb, acc[i][j + 1] + bb,
                                       acc[i][j + 2] + bb, acc[i][j + 3] + bb);
                *(float4*)&C[(size_t)row * N + col] = v;
            }
        }
    }
}

// ---------------- upsample combine: Y -> cond_raw ----------------------------------
__global__ void k_combine(const float* __restrict__ b_up)
{
    int idx = blockIdx.x * 256 + threadIdx.x;
    if (idx >= 2048 * T_LEN) return;
    int u = idx % T_LEN, o = idx / T_LEN;
    int p = u & 7, m = u >> 3;
    const float* Y = g_scratch + OFF_Y;
    g_scratch[OFF_CRAW + idx] =
        Y[(size_t)(o * 16 + p + 8) * 128 + m] +
        Y[(size_t)(o * 16 + p) * 128 + m + 1] + b_up[o];
}

// ---------------- one full WaveNet layer (dil conv + gate + res + skip) ------------
__global__ __launch_bounds__(128)
void k_layer(const float* __restrict__ w_dil_all, const float* __restrict__ b_dil_all,
             const float* __restrict__ w_res_all, const float* __restrict__ b_res_all,
             const float* __restrict__ w_skip_all, const float* __restrict__ b_skip_all,
             int layer)
{
    __shared__ float xs0[64][LT];
    __shared__ float xs1[64][LT];
    __shared__ float ws[32][128];
    __shared__ float ia_hi[64][LT];
    __shared__ float acts[64][LT];

    const int d = 1 << (layer & 7);
    const float* xin  = g_scratch + ((layer & 1) ? OFF_X1 : OFF_X0);
    float*       xout = g_scratch + ((layer & 1) ? OFF_X0 : OFF_X1);
    const float* cond = g_scratch + OFF_CACTS + (size_t)layer * 128 * T_LEN;
    float*       skip = g_scratch + OFF_SKIP;
    const float* w_dil  = w_dil_all  + (size_t)layer * 128 * 64 * 2;
    const float* b_dil  = b_dil_all  + layer * 128;
    const float* w_skip = w_skip_all + (size_t)layer * 256 * 64;
    const float* b_skip = b_skip_all + layer * 256;

    int t0 = blockIdx.x * LT;
    int c  = threadIdx.x;

    for (int idx = c; idx < 64 * LT; idx += 128) {
        int j = idx / LT, tt = idx % LT;
        int ta = t0 - d + tt;
        xs0[j][tt] = (ta >= 0 && ta < T_LEN) ? xin[(size_t)j * T_LEN + ta] : 0.0f;
        int tb = t0 + tt;
        xs1[j][tt] = (tb < T_LEN) ? xin[(size_t)j * T_LEN + tb] : 0.0f;
    }

    float acc[LT];
#pragma unroll
    for (int tt = 0; tt < LT; tt++) acc[tt] = 0.0f;

    for (int jc = 0; jc < 64; jc += 16) {
        __syncthreads();
        for (int idx = c; idx < 16 * 128 * 2; idx += 128) {
            int cc = idx >> 5;
            int r  = idx & 31;
            ws[r][cc] = w_dil[cc * 128 + jc * 2 + r];
        }
        __syncthreads();
#pragma unroll
        for (int jj = 0; jj < 16; jj++) {
            float w0 = ws[2 * jj][c];
            float w1 = ws[2 * jj + 1][c];
            const float4* p0 = (const float4*)&xs0[jc + jj][0];
            const float4* p1 = (const float4*)&xs1[jc + jj][0];
#pragma unroll
            for (int v = 0; v < 4; v++) {
                float4 a = p0[v]; float4 b = p1[v];
                acc[v * 4 + 0] += w0 * a.x + w1 * b.x;
                acc[v * 4 + 1] += w0 * a.y + w1 * b.y;
                acc[v * 4 + 2] += w0 * a.z + w1 * b.z;
                acc[v * 4 + 3] += w0 * a.w + w1 * b.w;
            }
        }
    }

    {
        float bd = b_dil[c];
#pragma unroll
        for (int tt = 0; tt < LT; tt++) {
            int t = t0 + tt;
            float cv = (t < T_LEN) ? cond[(size_t)c * T_LEN + t] : 0.0f;
            acc[tt] += bd + cv;
        }
    }
    __syncthreads();
    if (c >= 64) {
#pragma unroll
        for (int tt = 0; tt < LT; tt++) ia_hi[c - 64][tt] = acc[tt];
    }
    __syncthreads();
    if (c < 64) {
#pragma unroll
        for (int tt = 0; tt < LT; tt++) {
            float g  = ia_hi[c][tt];
            float sg = 1.0f / (1.0f + expf(-g));
            acts[c][tt] = tanhf(acc[tt]) * sg;
        }
    }
    __syncthreads();

    // residual (layers 0..14)
    if (layer < 15 && c < 64) {
        const float* w_res = w_res_all + (size_t)layer * 64 * 64;
        float r[LT];
#pragma unroll
        for (int tt = 0; tt < LT; tt++) r[tt] = 0.0f;
        for (int k = 0; k < 64; k++) {
            float w = w_res[c * 64 + k];
            const float4* ap = (const float4*)&acts[k][0];
#pragma unroll
            for (int v = 0; v < 4; v++) {
                float4 a = ap[v];
                r[v * 4 + 0] += w * a.x; r[v * 4 + 1] += w * a.y;
                r[v * 4 + 2] += w * a.z; r[v * 4 + 3] += w * a.w;
            }
        }
        float br = b_res_all[layer * 64 + c];
#pragma unroll
        for (int tt = 0; tt < LT; tt++) {
            int t = t0 + tt;
            if (t < T_LEN)
                xout[(size_t)c * T_LEN + t] = xin[(size_t)c * T_LEN + t] + r[tt] + br;
        }
    }

    // skip (all layers): 256 rows, 128 threads -> 2 rows each
#pragma unroll
    for (int rr = 0; rr < 2; rr++) {
        int row = c + rr * 128;
        float s[LT];
#pragma unroll
        for (int tt = 0; tt < LT; tt++) s[tt] = 0.0f;
        for (int k = 0; k < 64; k++) {
            float w = w_skip[row * 64 + k];
            const float4* ap = (const float4*)&acts[k][0];
#pragma unroll
            for (int v = 0; v < 4; v++) {
                float4 a = ap[v];
                s[v * 4 + 0] += w * a.x; s[v * 4 + 1] += w * a.y;
                s[v * 4 + 2] += w * a.z; s[v * 4 + 3] += w * a.w;
            }
        }
        float bs = b_skip[row];
#pragma unroll
        for (int tt = 0; tt < LT; tt++) {
            int t = t0 + tt;
            if (t < T_LEN) {
                size_t oidx = (size_t)row * T_LEN + t;
                float v = s[tt] + bs;
                skip[oidx] = (layer == 0) ? v : (skip[oidx] + v);
            }
        }
    }
}

// ---------------- head GEMM (256x256), optional relu / shifted store ---------------
__global__ __launch_bounds__(256)
void k_head(const float* __restrict__ in, const float* __restrict__ wT,
            float* __restrict__ out, int relu_in, int relu_out, int shifted)
{
    __shared__ float hs[256 * HT];
    int t0 = blockIdx.x * HT;
    int o  = threadIdx.x;
    for (int idx = o; idx < 256 * HT; idx += 256) {
        int cc = idx / HT, tt = idx % HT;
        int t = t0 + tt;
        float v = (t < T_LEN) ? in[(size_t)cc * T_LEN + t] : 0.0f;
        if (relu_in) v = fmaxf(v, 0.0f);
        hs[idx] = v;
    }
    __syncthreads();
    float acc[HT];
#pragma unroll
    for (int tt = 0; tt < HT; tt++) acc[tt] = 0.0f;
    for (int cc = 0; cc < 256; cc++) {
        float w = wT[cc * 256 + o];
        const float4* h4 = (const float4*)&hs[cc * HT];
#pragma unroll
        for (int v = 0; v < 4; v++) {
            float4 h = h4[v];
            acc[v * 4 + 0] += w * h.x; acc[v * 4 + 1] += w * h.y;
            acc[v * 4 + 2] += w * h.z; acc[v * 4 + 3] += w * h.w;
        }
    }
    if (shifted) {
        if (blockIdx.x == 0) out[(size_t)o * T_LEN] = 0.0f;
#pragma unroll
        for (int tt = 0; tt < HT; tt++) {
            int t = t0 + tt;
            if (t + 1 < T_LEN) out[(size_t)o * T_LEN + t + 1] = acc[tt];
        }
    } else {
#pragma unroll
        for (int tt = 0; tt < HT; tt++) {
            int t = t0 + tt;
            if (t < T_LEN) {
                float v = acc[tt];
                if (relu_out) v = fmaxf(v, 0.0f);
                out[(size_t)o * T_LEN + t] = v;
            }
        }
    }
}

// ---------------- launch ------------------------------------------------------------
extern "C" void kernel_launch(void* const* d_in, const int* in_sizes, int n_in,
                              void* d_out, int out_size)
{
    const float* features = (const float*)d_in[0];
    const float* audio    = (const float*)d_in[1];
    const float* w_up     = (const float*)d_in[2];
    const float* b_up     = (const float*)d_in[3];
    const float* w_cond   = (const float*)d_in[4];
    const float* b_cond   = (const float*)d_in[5];
    const float* embed    = (const float*)d_in[6];
    const float* w_dil    = (const float*)d_in[7];
    const float* b_dil    = (const float*)d_in[8];
    const float* w_res    = (const float*)d_in[9];
    const float* b_res    = (const float*)d_in[10];
    const float* w_skip   = (const float*)d_in[11];
    const float* b_skip   = (const float*)d_in[12];
    const float* w_out    = (const float*)d_in[13];
    const float* w_end    = (const float*)d_in[14];
    float* out = (float*)d_out;

    float* scr = nullptr;
    cudaGetSymbolAddress((void**)&scr, g_scratch);

    int write_q = (out_size >= 256 * T_LEN + T_LEN) ? 1 : 0;

    k_encode<<<(T_LEN + 255) / 256, 256>>>(audio, out + (size_t)256 * T_LEN, write_q);
    k_embed<<<(64 * T_LEN + 255) / 256, 256>>>(embed);

    dim3 tb(32, 8);
    k_transpose<<<dim3(2048 / 32, 2048 / 32), tb>>>(w_cond, scr + OFF_WCT, 2048, 2048);
    k_transpose<<<dim3(8, 8), tb>>>(w_out, scr + OFF_WOT, 256, 256);
    k_transpose<<<dim3(8, 8), tb>>>(w_end, scr + OFF_WET, 256, 256);

    // upsample GEMM: Y[32768,128] = w_up^T(as KxM) @ features
    k_gemm<<<dim3(32768 / 128, 1), 256>>>(w_up, features, scr + OFF_Y, nullptr,
                                          32768, 128, 2048);
    k_combine<<<(2048 * T_LEN + 255) / 256, 256>>>(b_up);

    // cond applied twice
    k_gemm<<<dim3(16, 8), 256>>>(scr + OFF_WCT, scr + OFF_CRAW, scr + OFF_C1,
                                 b_cond, 2048, T_LEN, 2048);
    k_gemm<<<dim3(16, 8), 256>>>(scr + OFF_WCT, scr + OFF_C1, scr + OFF_CACTS,
                                 b_cond, 2048, T_LEN, 2048);

    int lblocks = (T_LEN + LT - 1) / LT;
    for (int i = 0; i < 16; i++)
        k_layer<<<lblocks, 128>>>(w_dil, b_dil, w_res, b_res, w_skip, b_skip, i);

    int hblocks = (T_LEN + HT - 1) / HT;
    k_head<<<hblocks, 256>>>(scr + OFF_SKIP, scr + OFF_WOT, scr + OFF_H1, 1, 1, 0);
    k_head<<<hblocks, 256>>>(scr + OFF_H1, scr + OFF_WET, out, 0, 0, 1);
}

// round 3
// speedup vs baseline: 1.3001x; 1.3001x over previous
#include <cuda_runtime.h>
#include <cuda_bf16.h>
#include <math.h>
#include <stdint.h>

#define T_LEN 1016
#define LT 16
#define HT 16

// ---------------- scratch layout (float units) -------------------------------------
constexpr size_t OFF_WC_HI  = 0;                                  // bf16[2048*2048]
constexpr size_t OFF_WC_LO  = OFF_WC_HI  + 2097152;
constexpr size_t OFF_FT_HI  = OFF_WC_LO  + 2097152;               // bf16[128*2048]
constexpr size_t OFF_FT_LO  = OFF_FT_HI  + 131072;
constexpr size_t OFF_BR_HI  = OFF_FT_LO  + 131072;                // bf16[1024*2048]
constexpr size_t OFF_BR_LO  = OFF_BR_HI  + 1048576;
constexpr size_t OFF_B2_HI  = OFF_BR_LO  + 1048576;               // bf16[1024*2048]
constexpr size_t OFF_B2_LO  = OFF_B2_HI  + 1048576;
constexpr size_t OFF_CACTS  = OFF_B2_LO  + 1048576;               // f32[2048*1016]
constexpr size_t OFF_WOT    = OFF_CACTS  + 2080768;
constexpr size_t OFF_WET    = OFF_WOT    + 65536;
constexpr size_t OFF_X0     = OFF_WET    + 65536;
constexpr size_t OFF_X1     = OFF_X0     + 65024;
constexpr size_t OFF_SKIP   = OFF_X1     + 65024;
constexpr size_t OFF_H1     = OFF_SKIP   + 260096;
constexpr size_t OFF_Q      = OFF_H1     + 260096;
constexpr size_t SCRATCH_SZ = OFF_Q + 1024;

__device__ __align__(1024) float g_scratch[SCRATCH_SZ];

// ---------------- PTX helpers (baseline compute_103 features only) ------------------
__device__ __forceinline__ uint32_t s2u(const void* p) {
    uint32_t a;
    asm("{ .reg .u64 t; cvta.to.shared.u64 t, %1; cvt.u32.u64 %0, t; }" : "=r"(a) : "l"(p));
    return a;
}
__device__ __forceinline__ void cp16(uint32_t dst, const void* src) {
    asm volatile("cp.async.cg.shared.global [%0], [%1], 16;" :: "r"(dst), "l"(src));
}
#define CP_COMMIT() asm volatile("cp.async.commit_group;" ::: "memory")
#define CP_WAIT0()  asm volatile("cp.async.wait_group 0;" ::: "memory")

__device__ __forceinline__ void ldsm4(uint32_t* r, uint32_t a) {
    asm volatile("ldmatrix.sync.aligned.m8n8.x4.shared.b16 {%0,%1,%2,%3}, [%4];"
                 : "=r"(r[0]), "=r"(r[1]), "=r"(r[2]), "=r"(r[3]) : "r"(a));
}
__device__ __forceinline__ void ldsm4t(uint32_t* r, uint32_t a) {
    asm volatile("ldmatrix.sync.aligned.m8n8.x4.trans.shared.b16 {%0,%1,%2,%3}, [%4];"
                 : "=r"(r[0]), "=r"(r[1]), "=r"(r[2]), "=r"(r[3]) : "r"(a));
}
__device__ __forceinline__ void mma_bf16(float* c, const uint32_t* a, const uint32_t* b) {
    asm volatile("mma.sync.aligned.m16n8k16.row.col.f32.bf16.bf16.f32 "
                 "{%0,%1,%2,%3}, {%4,%5,%6,%7}, {%8,%9}, {%0,%1,%2,%3};"
                 : "+f"(c[0]), "+f"(c[1]), "+f"(c[2]), "+f"(c[3])
                 : "r"(a[0]), "r"(a[1]), "r"(a[2]), "r"(a[3]), "r"(b[0]), "r"(b[1]));
}

// smem tile addressing (bytes). k-major tile: 128 rows x 32 bf16 (64B rows).
__device__ __forceinline__ uint32_t off_km(int row, int kk) {
    return (uint32_t)(row * 64 + ((kk ^ ((row >> 1) & 3)) << 4));
}
// trans tile: 32 k-rows x 128 m (256B rows), 16B chunks mc 0..15
__device__ __forceinline__ uint32_t off_tr(int k, int mc) {
    return (uint32_t)(k * 256 + ((mc ^ (k & 7)) << 4));
}
__device__ __forceinline__ uint32_t bpack(float x, float y) {
    uint32_t lo = (uint32_t)__bfloat16_as_ushort(__float2bfloat16(x));
    uint32_t hi = (uint32_t)__bfloat16_as_ushort(__float2bfloat16(y));
    return lo | (hi << 16);
}

// ---------------- mu-law encode + q output ------------------------------------------
__global__ void k_encode(const float* __restrict__ audio, float* __restrict__ q_out,
                         int write_q)
{
    int t = blockIdx.x * 256 + threadIdx.x;
    if (t >= T_LEN) return;
    float x = audio[t];
    float xc = fminf(1.0f, fmaxf(-1.0f, x));
    float s  = (xc > 0.0f) ? 1.0f : ((xc < 0.0f) ? -1.0f : 0.0f);
    float num = log1pf(__fmul_rn(255.0f, fabsf(xc)));
    float den = log1pf(255.0f);
    float m = __fdiv_rn(__fmul_rn(s, num), den);
    float v = __fadd_rn(__fmul_rn(__fmul_rn(__fadd_rn(m, 1.0f), 0.5f), 255.0f), 0.5f);
    v = fminf(255.0f, fmaxf(0.0f, v));
    int q = (int)v;
    ((int*)(g_scratch + OFF_Q))[t] = q;
    if (write_q) q_out[t] = (float)q;
}

// ---------------- embedding lookup -> x0 (64 x T) -----------------------------------
__global__ void k_embed(const float* __restrict__ embed)
{
    int idx = blockIdx.x * 256 + threadIdx.x;
    if (idx >= 64 * T_LEN) return;
    int t = idx % T_LEN, j = idx / T_LEN;
    int q = ((const int*)(g_scratch + OFF_Q))[t];
    g_scratch[OFF_X0 + (size_t)j * T_LEN + t] = embed[q * 64 + j];
}

// ---------------- transpose fp32 (R x C -> C x R) -----------------------------------
__global__ void k_transpose(const float* __restrict__ in, float* __restrict__ out,
                            int R, int C)
{
    __shared__ float tile[32][33];
    int c0 = blockIdx.x * 32, r0 = blockIdx.y * 32;
    int x = threadIdx.x, y = threadIdx.y;
#pragma unroll
    for (int i = 0; i < 32; i += 8)
        tile[y + i][x] = in[(size_t)(r0 + y + i) * C + c0 + x];
    __syncthreads();
#pragma unroll
    for (int i = 0; i < 32; i += 8)
        out[(size_t)(c0 + y + i) * R + r0 + x] = tile[x][y + i];
}

// ---------------- transpose + bf16 hi/lo split: in[R][C] -> out[C][R] ----------------
__global__ void k_tsplit(const float* __restrict__ in, __nv_bfloat16* __restrict__ hi,
                         __nv_bfloat16* __restrict__ lo, int R, int C)
{
    __shared__ float tile[32][33];
    int c0 = blockIdx.x * 32, r0 = blockIdx.y * 32;
    int x = threadIdx.x, y = threadIdx.y;
#pragma unroll
    for (int i = 0; i < 32; i += 8)
        tile[y + i][x] = in[(size_t)(r0 + y + i) * C + c0 + x];
    __syncthreads();
#pragma unroll
    for (int i = 0; i < 32; i += 8) {
        float v = tile[x][y + i];
        size_t o = (size_t)(c0 + y + i) * R + r0 + x;
        __nv_bfloat16 h = __float2bfloat16(v);
        hi[o] = h;
        lo[o] = __float2bfloat16(v - __bfloat162float(h));
    }
}

// ---------------- elementwise bf16 hi/lo split ---------------------------------------
__global__ void k_split(const float* __restrict__ in, __nv_bfloat16* __restrict__ hi,
                        __nv_bfloat16* __restrict__ lo, int n)
{
    int i = blockIdx.x * 256 + threadIdx.x;
    if (i >= n) return;
    float v = in[i];
    __nv_bfloat16 h = __float2bfloat16(v);
    hi[i] = h;
    lo[i] = __float2bfloat16(v - __bfloat162float(h));
}

// ---------------- mma.sync split-bf16 GEMM: D[m][n] = sum_k A[m][k] B[n][k] ---------
// afp32 = 1: A is fp32 [K][Mg] (w_up flattened); loaded+split in-kernel (trans tile)
// mode 0: fused upsample-combine epilogue -> cond_raw^T hi/lo [1016][2048]
// mode 1: +bias, write hi/lo transposed [n][2048] at col bm
// mode 2: +bias, write fp32 [m][1016]
__global__ __launch_bounds__(256)
void k_gemm_tc(const __nv_bfloat16* __restrict__ Ahi, const __nv_bfloat16* __restrict__ Alo,
               const float* __restrict__ Af32, int Mg, int afp32,
               const __nv_bfloat16* __restrict__ Bhi, const __nv_bfloat16* __restrict__ Blo,
               int K, int mode, const float* __restrict__ bias,
               float* __restrict__ outF,
               __nv_bfloat16* __restrict__ outHi, __nv_bfloat16* __restrict__ outLo)
{
    extern __shared__ char smem[];
    uint32_t sb = s2u(smem);
    const int tid = threadIdx.x;
    const int wid = tid >> 5, lane = tid & 31;
    const int bm = blockIdx.x * 128, bn = blockIdx.y * 128;
    const int wm = (wid >> 1) * 32, wn = (wid & 1) * 64;

    // smem byte offsets (single stage, 32KB)
    const uint32_t A_HI = 0, A_LO = 8192, B_HI = 16384, B_LO = 24576;

    float acc[2][8][4];
#pragma unroll
    for (int mt = 0; mt < 2; mt++)
#pragma unroll
        for (int nt = 0; nt < 8; nt++)
#pragma unroll
            for (int i = 0; i < 4; i++) acc[mt][nt][i] = 0.0f;

    for (int k0 = 0; k0 < K; k0 += 32) {
        // ---- load stage ----
        if (afp32) {
#pragma unroll
            for (int i = 0; i < 4; i++) {
                int u = tid + i * 256;            // 1024 float4 units
                int k = u >> 5, f4 = u & 31;
                float4 v = *reinterpret_cast<const float4*>(
                    Af32 + (size_t)(k0 + k) * Mg + bm + f4 * 4);
                __nv_bfloat16 h0 = __float2bfloat16(v.x), h1 = __float2bfloat16(v.y);
                __nv_bfloat16 h2 = __float2bfloat16(v.z), h3 = __float2bfloat16(v.w);
                uint32_t hi01 = (uint32_t)__bfloat16_as_ushort(h0) |
                                ((uint32_t)__bfloat16_as_ushort(h1) << 16);
                uint32_t hi23 = (uint32_t)__bfloat16_as_ushort(h2) |
                                ((uint32_t)__bfloat16_as_ushort(h3) << 16);
                uint32_t lo01 = bpack(v.x - __bfloat162float(h0), v.y - __bfloat162float(h1));
                uint32_t lo23 = bpack(v.z - __bfloat162float(h2), v.w - __bfloat162float(h3));
                int mc = f4 >> 1, half = f4 & 1;
                uint32_t a = off_tr(k, mc) + half * 8;
                *reinterpret_cast<uint2*>(smem + A_HI + a) = make_uint2(hi01, hi23);
                *reinterpret_cast<uint2*>(smem + A_LO + a) = make_uint2(lo01, lo23);
            }
#pragma unroll
            for (int i = 0; i < 2; i++) {
                int idx = tid + i * 256;          // 512 chunks: 128 rows x 4 kk
                int row = idx >> 2, kk = idx & 3;
                uint32_t d = off_km(row, kk);
                const __nv_bfloat16* sh = Bhi + (size_t)(bn + row) * K + k0 + kk * 8;
                const __nv_bfloat16* sl = Blo + (size_t)(bn + row) * K + k0 + kk * 8;
                cp16(sb + B_HI + d, sh);
                cp16(sb + B_LO + d, sl);
            }
        } else {
#pragma unroll
            for (int i = 0; i < 2; i++) {
                int idx = tid + i * 256;
                int row = idx >> 2, kk = idx & 3;
                uint32_t dk = off_km(row, kk);
                size_t ao = (size_t)(bm + row) * K + k0 + kk * 8;
                size_t bo = (size_t)(bn + row) * K + k0 + kk * 8;
                cp16(sb + A_HI + dk, Ahi + ao);
                cp16(sb + A_LO + dk, Alo + ao);
                cp16(sb + B_HI + dk, Bhi + bo);
                cp16(sb + B_LO + dk, Blo + bo);
            }
        }
        CP_COMMIT();
        CP_WAIT0();
        __syncthreads();

        // ---- compute 2 x k16 ----
#pragma unroll
        for (int s = 0; s < 2; s++) {
            const int kk0 = s * 2;
            uint32_t af[2][2][4];   // [mt][hi/lo][4]
#pragma unroll
            for (int mt = 0; mt < 2; mt++) {
                uint32_t ad;
                if (afp32) {
                    int k  = s * 16 + ((lane >> 4) << 3) + (lane & 7);
                    int mc = ((wm + mt * 16) >> 3) + ((lane >> 3) & 1);
                    ad = off_tr(k, mc);
                    ldsm4t(af[mt][0], sb + A_HI + ad);
                    ldsm4t(af[mt][1], sb + A_LO + ad);
                } else {
                    int row = wm + mt * 16 + (lane & 15);
                    int kk  = kk0 + (lane >> 4);
                    ad = off_km(row, kk);
                    ldsm4(af[mt][0], sb + A_HI + ad);
                    ldsm4(af[mt][1], sb + A_LO + ad);
                }
            }
            uint32_t bh[8][2], bl[8][2];
#pragma unroll
            for (int p = 0; p < 4; p++) {
                int nb  = wn + p * 16;
                int row = nb + ((lane >> 4) << 3) + (lane & 7);
                int kk  = kk0 + ((lane >> 3) & 1);
                uint32_t bd = off_km(row, kk);
                uint32_t r[4];
                ldsm4(r, sb + B_HI + bd);
                bh[2 * p][0] = r[0]; bh[2 * p][1] = r[1];
                bh[2 * p + 1][0] = r[2]; bh[2 * p + 1][1] = r[3];
                ldsm4(r, sb + B_LO + bd);
                bl[2 * p][0] = r[0]; bl[2 * p][1] = r[1];
                bl[2 * p + 1][0] = r[2]; bl[2 * p + 1][1] = r[3];
            }
#pragma unroll
            for (int mt = 0; mt < 2; mt++)
#pragma unroll
                for (int nt = 0; nt < 8; nt++) {
                    mma_bf16(acc[mt][nt], af[mt][0], bh[nt]);
                    mma_bf16(acc[mt][nt], af[mt][0], bl[nt]);
                    mma_bf16(acc[mt][nt], af[mt][1], bh[nt]);
                }
        }
        __syncthreads();
    }

    // ---- stage D (128x128) to smem, stride 129 ----
    float* sd = reinterpret_cast<float*>(smem);
#pragma unroll
    for (int mt = 0; mt < 2; mt++)
#pragma unroll
        for (int nt = 0; nt < 8; nt++) {
            int r = wm + mt * 16 + (lane >> 2);
            int c = wn + nt * 8 + (lane & 3) * 2;
            sd[r * 129 + c]           = acc[mt][nt][0];
            sd[r * 129 + c + 1]       = acc[mt][nt][1];
            sd[(r + 8) * 129 + c]     = acc[mt][nt][2];
            sd[(r + 8) * 129 + c + 1] = acc[mt][nt][3];
        }
    __syncthreads();

    if (mode == 0) {
        int bo = bm >> 4;
        for (int u = tid; u < T_LEN; u += 256) {
            int m = u >> 3, p = u & 7;
            uint4 vh, vl;
            __nv_bfloat16* hp = (__nv_bfloat16*)&vh;
            __nv_bfloat16* lp = (__nv_bfloat16*)&vl;
#pragma unroll
            for (int ol = 0; ol < 8; ol++) {
                float v = sd[(ol * 16 + p + 8) * 129 + m] +
                          sd[(ol * 16 + p) * 129 + m + 1] + bias[bo + ol];
                __nv_bfloat16 h = __float2bfloat16(v);
                hp[ol] = h;
                lp[ol] = __float2bfloat16(v - __bfloat162float(h));
            }
            *reinterpret_cast<uint4*>(outHi + (size_t)u * 2048 + bo) = vh;
            *reinterpret_cast<uint4*>(outLo + (size_t)u * 2048 + bo) = vl;
        }
    } else if (mode == 1) {
        int mg = (tid & 31) * 4;
        int nl = tid >> 5;
        for (int n0 = 0; n0 < 128; n0 += 8) {
            int n = n0 + nl;
            uint2 vh, vl;
            __nv_bfloat16* hp = (__nv_bfloat16*)&vh;
            __nv_bfloat16* lp = (__nv_bfloat16*)&vl;
#pragma unroll
            for (int j = 0; j < 4; j++) {
                float v = sd[(mg + j) * 129 + n] + bias[bm + mg + j];
                __nv_bfloat16 h = __float2bfloat16(v);
                hp[j] = h;
                lp[j] = __float2bfloat16(v - __bfloat162float(h));
            }
            *reinterpret_cast<uint2*>(outHi + (size_t)(bn + n) * 2048 + bm + mg) = vh;
            *reinterpret_cast<uint2*>(outLo + (size_t)(bn + n) * 2048 + bm + mg) = vl;
        }
    } else {
        int mo = tid >> 7, n = tid & 127;
        int gn = bn + n;
        if (gn < T_LEN) {
            for (int m0 = 0; m0 < 128; m0 += 2) {
                int m = m0 + mo;
                outF[(size_t)(bm + m) * T_LEN + gn] = sd[m * 129 + n] + bias[bm + m];
            }
        }
    }
}

// ---------------- one full WaveNet layer (dil conv + gate + res + skip) --------------
__global__ __launch_bounds__(128)
void k_layer(const float* __restrict__ w_dil_all, const float* __restrict__ b_dil_all,
             const float* __restrict__ w_res_all, const float* __restrict__ b_res_all,
             const float* __restrict__ w_skip_all, const float* __restrict__ b_skip_all,
             int layer)
{
    __shared__ float xs0[64][LT];
    __shared__ float xs1[64][LT];
    __shared__ float ws[32][128];
    __shared__ float ia_hi[64][LT];
    __shared__ float acts[64][LT];

    const int d = 1 << (layer & 7);
    const float* xin  = g_scratch + ((layer & 1) ? OFF_X1 : OFF_X0);
    float*       xout = g_scratch + ((layer & 1) ? OFF_X0 : OFF_X1);
    const float* cond = g_scratch + OFF_CACTS + (size_t)layer * 128 * T_LEN;
    float*       skip = g_scratch + OFF_SKIP;
    const float* w_dil  = w_dil_all  + (size_t)layer * 128 * 64 * 2;
    const float* b_dil  = b_dil_all  + layer * 128;
    const float* w_skip = w_skip_all + (size_t)layer * 256 * 64;
    const float* b_skip = b_skip_all + layer * 256;

    int t0 = blockIdx.x * LT;
    int c  = threadIdx.x;

    for (int idx = c; idx < 64 * LT; idx += 128) {
        int j = idx / LT, tt = idx % LT;
        int ta = t0 - d + tt;
        xs0[j][tt] = (ta >= 0 && ta < T_LEN) ? xin[(size_t)j * T_LEN + ta] : 0.0f;
        int tb = t0 + tt;
        xs1[j][tt] = (tb < T_LEN) ? xin[(size_t)j * T_LEN + tb] : 0.0f;
    }

    float acc[LT];
#pragma unroll
    for (int tt = 0; tt < LT; tt++) acc[tt] = 0.0f;

    for (int jc = 0; jc < 64; jc += 16) {
        __syncthreads();
        for (int idx = c; idx < 16 * 128 * 2; idx += 128) {
            int cc = idx >> 5;
            int r  = idx & 31;
            ws[r][cc] = w_dil[cc * 128 + jc * 2 + r];
        }
        __syncthreads();
#pragma unroll
        for (int jj = 0; jj < 16; jj++) {
            float w0 = ws[2 * jj][c];
            float w1 = ws[2 * jj + 1][c];
            const float4* p0 = (const float4*)&xs0[jc + jj][0];
            const float4* p1 = (const float4*)&xs1[jc + jj][0];
#pragma unroll
            for (int v = 0; v < 4; v++) {
                float4 a = p0[v]; float4 b = p1[v];
                acc[v * 4 + 0] += w0 * a.x + w1 * b.x;
                acc[v * 4 + 1] += w0 * a.y + w1 * b.y;
                acc[v * 4 + 2] += w0 * a.z + w1 * b.z;
                acc[v * 4 + 3] += w0 * a.w + w1 * b.w;
            }
        }
    }

    {
        float bd = b_dil[c];
#pragma unroll
        for (int tt = 0; tt < LT; tt++) {
            int t = t0 + tt;
            float cv = (t < T_LEN) ? cond[(size_t)c * T_LEN + t] : 0.0f;
            acc[tt] += bd + cv;
        }
    }
    __syncthreads();
    if (c >= 64) {
#pragma unroll
        for (int tt = 0; tt < LT; tt++) ia_hi[c - 64][tt] = acc[tt];
    }
    __syncthreads();
    if (c < 64) {
#pragma unroll
        for (int tt = 0; tt < LT; tt++) {
            float g  = ia_hi[c][tt];
            float sg = 1.0f / (1.0f + expf(-g));
            acts[c][tt] = tanhf(acc[tt]) * sg;
        }
    }
    __syncthreads();

    if (layer < 15 && c < 64) {
        const float* w_res = w_res_all + (size_t)layer * 64 * 64;
        float r[LT];
#pragma unroll
        for (int tt = 0; tt < LT; tt++) r[tt] = 0.0f;
        for (int k = 0; k < 64; k++) {
            float w = w_res[c * 64 + k];
            const float4* ap = (const float4*)&acts[k][0];
#pragma unroll
            for (int v = 0; v < 4; v++) {
                float4 a = ap[v];
                r[v * 4 + 0] += w * a.x; r[v * 4 + 1] += w * a.y;
                r[v * 4 + 2] += w * a.z; r[v * 4 + 3] += w * a.w;
            }
        }
        float br = b_res_all[layer * 64 + c];
#pragma unroll
        for (int tt = 0; tt < LT; tt++) {
            int t = t0 + tt;
            if (t < T_LEN)
                xout[(size_t)c * T_LEN + t] = xin[(size_t)c * T_LEN + t] + r[tt] + br;
        }
    }

#pragma unroll
    for (int rr = 0; rr < 2; rr++) {
        int row = c + rr * 128;
        float s[LT];
#pragma unroll
        for (int tt = 0; tt < LT; tt++) s[tt] = 0.0f;
        for (int k = 0; k < 64; k++) {
            float w = w_skip[row * 64 + k];
            const float4* ap = (const float4*)&acts[k][0];
#pragma unroll
            for (int v = 0; v < 4; v++) {
                float4 a = ap[v];
                s[v * 4 + 0] += w * a.x; s[v * 4 + 1] += w * a.y;
                s[v * 4 + 2] += w * a.z; s[v * 4 + 3] += w * a.w;
            }
        }
        float bs = b_skip[row];
#pragma unroll
        for (int tt = 0; tt < LT; tt++) {
            int t = t0 + tt;
            if (t < T_LEN) {
                size_t oidx = (size_t)row * T_LEN + t;
                float v = s[tt] + bs;
                skip[oidx] = (layer == 0) ? v : (skip[oidx] + v);
            }
        }
    }
}

// ---------------- head GEMM (256x256), optional relu / shifted store -----------------
__global__ __launch_bounds__(256)
void k_head(const float* __restrict__ in, const float* __restrict__ wT,
            float* __restrict__ out, int relu_in, int relu_out, int shifted)
{
    __shared__ float hs[256 * HT];
    int t0 = blockIdx.x * HT;
    int o  = threadIdx.x;
    for (int idx = o; idx < 256 * HT; idx += 256) {
        int cc = idx / HT, tt = idx % HT;
        int t = t0 + tt;
        float v = (t < T_LEN) ? in[(size_t)cc * T_LEN + t] : 0.0f;
        if (relu_in) v = fmaxf(v, 0.0f);
        hs[idx] = v;
    }
    __syncthreads();
    float acc[HT];
#pragma unroll
    for (int tt = 0; tt < HT; tt++) acc[tt] = 0.0f;
    for (int cc = 0; cc < 256; cc++) {
        float w = wT[cc * 256 + o];
        const float4* h4 = (const float4*)&hs[cc * HT];
#pragma unroll
        for (int v = 0; v < 4; v++) {
            float4 h = h4[v];
            acc[v * 4 + 0] += w * h.x; acc[v * 4 + 1] += w * h.y;
            acc[v * 4 + 2] += w * h.z; acc[v * 4 + 3] += w * h.w;
        }
    }
    if (shifted) {
        if (blockIdx.x == 0) out[(size_t)o * T_LEN] = 0.0f;
#pragma unroll
        for (int tt = 0; tt < HT; tt++) {
            int t = t0 + tt;
            if (t + 1 < T_LEN) out[(size_t)o * T_LEN + t + 1] = acc[tt];
        }
    } else {
#pragma unroll
        for (int tt = 0; tt < HT; tt++) {
            int t = t0 + tt;
            if (t < T_LEN) {
                float v = acc[tt];
                if (relu_out) v = fmaxf(v, 0.0f);
                out[(size_t)o * T_LEN + t] = v;
            }
        }
    }
}

// ---------------- launch -------------------------------------------------------------
extern "C" void kernel_launch(void* const* d_in, const int* in_sizes, int n_in,
                              void* d_out, int out_size)
{
    const float* features = (const float*)d_in[0];
    const float* audio    = (const float*)d_in[1];
    const float* w_up     = (const float*)d_in[2];
    const float* b_up     = (const float*)d_in[3];
    const float* w_cond   = (const float*)d_in[4];
    const float* b_cond   = (const float*)d_in[5];
    const float* embed    = (const float*)d_in[6];
    const float* w_dil    = (const float*)d_in[7];
    const float* b_dil    = (const float*)d_in[8];
    const float* w_res    = (const float*)d_in[9];
    const float* b_res    = (const float*)d_in[10];
    const float* w_skip   = (const float*)d_in[11];
    const float* b_skip   = (const float*)d_in[12];
    const float* w_out    = (const float*)d_in[13];
    const float* w_end    = (const float*)d_in[14];
    float* out = (float*)d_out;

    float* scr = nullptr;
    cudaGetSymbolAddress((void**)&scr, g_scratch);

    __nv_bfloat16* WC_HI = (__nv_bfloat16*)(scr + OFF_WC_HI);
    __nv_bfloat16* WC_LO = (__nv_bfloat16*)(scr + OFF_WC_LO);
    __nv_bfloat16* FT_HI = (__nv_bfloat16*)(scr + OFF_FT_HI);
    __nv_bfloat16* FT_LO = (__nv_bfloat16*)(scr + OFF_FT_LO);
    __nv_bfloat16* BR_HI = (__nv_bfloat16*)(scr + OFF_BR_HI);
    __nv_bfloat16* BR_LO = (__nv_bfloat16*)(scr + OFF_BR_LO);
    __nv_bfloat16* B2_HI = (__nv_bfloat16*)(scr + OFF_B2_HI);
    __nv_bfloat16* B2_LO = (__nv_bfloat16*)(scr + OFF_B2_LO);

    cudaFuncSetAttribute(k_gemm_tc, cudaFuncAttributeMaxDynamicSharedMemorySize, 67584);

    int write_q = (out_size >= 256 * T_LEN + T_LEN) ? 1 : 0;

    k_encode<<<(T_LEN + 255) / 256, 256>>>(audio, out + (size_t)256 * T_LEN, write_q);
    k_embed<<<(64 * T_LEN + 255) / 256, 256>>>(embed);

    dim3 tb(32, 8);
    k_transpose<<<dim3(8, 8), tb>>>(w_out, scr + OFF_WOT, 256, 256);
    k_transpose<<<dim3(8, 8), tb>>>(w_end, scr + OFF_WET, 256, 256);

    k_tsplit<<<dim3(4, 64), tb>>>(features, FT_HI, FT_LO, 2048, 128);
    k_split<<<(2048 * 2048) / 256, 256>>>(w_cond, WC_HI, WC_LO, 2048 * 2048);

    // upsample GEMM (A = w_up fp32 direct) + fused combine -> cond_raw^T hi/lo
    k_gemm_tc<<<dim3(256, 1), 256, 67584>>>(nullptr, nullptr, w_up, 32768, 1,
                                            FT_HI, FT_LO, 2048, 0,
                                            b_up, nullptr, BR_HI, BR_LO);
    // cond GEMM #1 -> cond1^T hi/lo
    k_gemm_tc<<<dim3(16, 8), 256, 67584>>>(WC_HI, WC_LO, nullptr, 0, 0,
                                           BR_HI, BR_LO, 2048, 1,
                                           b_cond, nullptr, B2_HI, B2_LO);
    // cond GEMM #2 -> cond_acts fp32 [2048][1016]
    k_gemm_tc<<<dim3(16, 8), 256, 67584>>>(WC_HI, WC_LO, nullptr, 0, 0,
                                           B2_HI, B2_LO, 2048, 2,
                                           b_cond, scr + OFF_CACTS, nullptr, nullptr);

    int lblocks = (T_LEN + LT - 1) / LT;
    for (int i = 0; i < 16; i++)
        k_layer<<<lblocks, 128>>>(w_dil, b_dil, w_res, b_res, w_skip, b_skip, i);

    int hblocks = (T_LEN + HT - 1) / HT;
    k_head<<<hblocks, 256>>>(scr + OFF_SKIP, scr + OFF_WOT, scr + OFF_H1, 1, 1, 0);
    k_head<<<hblocks, 256>>>(scr + OFF_H1, scr + OFF_WET, out, 0, 0, 1);
}

// round 4
// speedup vs baseline: 1.5179x; 1.1675x over previous
#include <cuda_runtime.h>
#include <cuda_bf16.h>
#include <math.h>
#include <stdint.h>

#define T_LEN 1016
#define LT 16
#define HT 16

// ---------------- scratch layout (float units) -------------------------------------
constexpr size_t OFF_WC_HI  = 0;                                  // bf16[2048*2048]
constexpr size_t OFF_WC_LO  = OFF_WC_HI  + 2097152;
constexpr size_t OFF_FT_HI  = OFF_WC_LO  + 2097152;               // bf16[128*2048]
constexpr size_t OFF_FT_LO  = OFF_FT_HI  + 131072;
constexpr size_t OFF_BR_HI  = OFF_FT_LO  + 131072;                // bf16[1024*2048]
constexpr size_t OFF_BR_LO  = OFF_BR_HI  + 1048576;
constexpr size_t OFF_B2_HI  = OFF_BR_LO  + 1048576;               // bf16[1024*2048]
constexpr size_t OFF_B2_LO  = OFF_B2_HI  + 1048576;
constexpr size_t OFF_CACTS  = OFF_B2_LO  + 1048576;               // f32[2048*1016]
constexpr size_t OFF_WOT    = OFF_CACTS  + 2080768;
constexpr size_t OFF_WET    = OFF_WOT    + 65536;
constexpr size_t OFF_X0     = OFF_WET    + 65536;
constexpr size_t OFF_X1     = OFF_X0     + 65024;
constexpr size_t OFF_SKIP   = OFF_X1     + 65024;
constexpr size_t OFF_H1     = OFF_SKIP   + 260096;
constexpr size_t OFF_Q      = OFF_H1     + 260096;
constexpr size_t OFF_WSKT   = OFF_Q      + 1024;                  // f32[16][64][256]
constexpr size_t OFF_WRST   = OFF_WSKT   + 262144;                // f32[15][64][64]
constexpr size_t SCRATCH_SZ = OFF_WRST + 61440;

__device__ __align__(1024) float g_scratch[SCRATCH_SZ];

// ---------------- PTX helpers (baseline compute_103 features only) ------------------
__device__ __forceinline__ uint32_t s2u(const void* p) {
    uint32_t a;
    asm("{ .reg .u64 t; cvta.to.shared.u64 t, %1; cvt.u32.u64 %0, t; }" : "=r"(a) : "l"(p));
    return a;
}
__device__ __forceinline__ void cp16(uint32_t dst, const void* src) {
    asm volatile("cp.async.cg.shared.global [%0], [%1], 16;" :: "r"(dst), "l"(src));
}
#define CP_COMMIT() asm volatile("cp.async.commit_group;" ::: "memory")

__device__ __forceinline__ void ldsm4(uint32_t* r, uint32_t a) {
    asm volatile("ldmatrix.sync.aligned.m8n8.x4.shared.b16 {%0,%1,%2,%3}, [%4];"
                 : "=r"(r[0]), "=r"(r[1]), "=r"(r[2]), "=r"(r[3]) : "r"(a));
}
__device__ __forceinline__ void ldsm4t(uint32_t* r, uint32_t a) {
    asm volatile("ldmatrix.sync.aligned.m8n8.x4.trans.shared.b16 {%0,%1,%2,%3}, [%4];"
                 : "=r"(r[0]), "=r"(r[1]), "=r"(r[2]), "=r"(r[3]) : "r"(a));
}
__device__ __forceinline__ void mma_bf16(float* c, const uint32_t* a, const uint32_t* b) {
    asm volatile("mma.sync.aligned.m16n8k16.row.col.f32.bf16.bf16.f32 "
                 "{%0,%1,%2,%3}, {%4,%5,%6,%7}, {%8,%9}, {%0,%1,%2,%3};"
                 : "+f"(c[0]), "+f"(c[1]), "+f"(c[2]), "+f"(c[3])
                 : "r"(a[0]), "r"(a[1]), "r"(a[2]), "r"(a[3]), "r"(b[0]), "r"(b[1]));
}

// k-major tile: 128 rows x 32 bf16 (64B rows), swizzled
__device__ __forceinline__ uint32_t off_km(int row, int kk) {
    return (uint32_t)(row * 64 + ((kk ^ ((row >> 1) & 3)) << 4));
}
// trans tile: 32 k-rows x 128 m (256B rows), 16B chunks mc 0..15
__device__ __forceinline__ uint32_t off_tr(int k, int mc) {
    return (uint32_t)(k * 256 + ((mc ^ (k & 7)) << 4));
}
__device__ __forceinline__ uint32_t bpack(float x, float y) {
    uint32_t lo = (uint32_t)__bfloat16_as_ushort(__float2bfloat16(x));
    uint32_t hi = (uint32_t)__bfloat16_as_ushort(__float2bfloat16(y));
    return lo | (hi << 16);
}

// ---------------- mu-law encode + q output ------------------------------------------
__global__ void k_encode(const float* __restrict__ audio, float* __restrict__ q_out,
                         int write_q)
{
    int t = blockIdx.x * 256 + threadIdx.x;
    if (t >= T_LEN) return;
    float x = audio[t];
    float xc = fminf(1.0f, fmaxf(-1.0f, x));
    float s  = (xc > 0.0f) ? 1.0f : ((xc < 0.0f) ? -1.0f : 0.0f);
    float num = log1pf(__fmul_rn(255.0f, fabsf(xc)));
    float den = log1pf(255.0f);
    float m = __fdiv_rn(__fmul_rn(s, num), den);
    float v = __fadd_rn(__fmul_rn(__fmul_rn(__fadd_rn(m, 1.0f), 0.5f), 255.0f), 0.5f);
    v = fminf(255.0f, fmaxf(0.0f, v));
    int q = (int)v;
    ((int*)(g_scratch + OFF_Q))[t] = q;
    if (write_q) q_out[t] = (float)q;
}

// ---------------- embedding lookup -> x0 (64 x T) -----------------------------------
__global__ void k_embed(const float* __restrict__ embed)
{
    int idx = blockIdx.x * 256 + threadIdx.x;
    if (idx >= 64 * T_LEN) return;
    int t = idx % T_LEN, j = idx / T_LEN;
    int q = ((const int*)(g_scratch + OFF_Q))[t];
    g_scratch[OFF_X0 + (size_t)j * T_LEN + t] = embed[q * 64 + j];
}

// ---------------- transpose fp32 (R x C -> C x R) -----------------------------------
__global__ void k_transpose(const float* __restrict__ in, float* __restrict__ out,
                            int R, int C)
{
    __shared__ float tile[32][33];
    int c0 = blockIdx.x * 32, r0 = blockIdx.y * 32;
    int x = threadIdx.x, y = threadIdx.y;
#pragma unroll
    for (int i = 0; i < 32; i += 8)
        tile[y + i][x] = in[(size_t)(r0 + y + i) * C + c0 + x];
    __syncthreads();
#pragma unroll
    for (int i = 0; i < 32; i += 8)
        out[(size_t)(c0 + y + i) * R + r0 + x] = tile[x][y + i];
}

// ---------------- batched transpose (per-layer weights) ------------------------------
__global__ void k_transpose_b(const float* __restrict__ in, float* __restrict__ out,
                              int R, int C, size_t inL, size_t outL)
{
    __shared__ float tile[32][33];
    int l = blockIdx.z;
    const float* ip = in + (size_t)l * inL;
    float* op = out + (size_t)l * outL;
    int c0 = blockIdx.x * 32, r0 = blockIdx.y * 32;
    int x = threadIdx.x, y = threadIdx.y;
#pragma unroll
    for (int i = 0; i < 32; i += 8)
        tile[y + i][x] = ip[(size_t)(r0 + y + i) * C + c0 + x];
    __syncthreads();
#pragma unroll
    for (int i = 0; i < 32; i += 8)
        op[(size_t)(c0 + y + i) * R + r0 + x] = tile[x][y + i];
}

// ---------------- transpose + bf16 hi/lo split: in[R][C] -> out[C][R] ----------------
__global__ void k_tsplit(const float* __restrict__ in, __nv_bfloat16* __restrict__ hi,
                         __nv_bfloat16* __restrict__ lo, int R, int C)
{
    __shared__ float tile[32][33];
    int c0 = blockIdx.x * 32, r0 = blockIdx.y * 32;
    int x = threadIdx.x, y = threadIdx.y;
#pragma unroll
    for (int i = 0; i < 32; i += 8)
        tile[y + i][x] = in[(size_t)(r0 + y + i) * C + c0 + x];
    __syncthreads();
#pragma unroll
    for (int i = 0; i < 32; i += 8) {
        float v = tile[x][y + i];
        size_t o = (size_t)(c0 + y + i) * R + r0 + x;
        __nv_bfloat16 h = __float2bfloat16(v);
        hi[o] = h;
        lo[o] = __float2bfloat16(v - __bfloat162float(h));
    }
}

// ---------------- elementwise bf16 hi/lo split ---------------------------------------
__global__ void k_split(const float* __restrict__ in, __nv_bfloat16* __restrict__ hi,
                        __nv_bfloat16* __restrict__ lo, int n)
{
    int i = blockIdx.x * 256 + threadIdx.x;
    if (i >= n) return;
    float v = in[i];
    __nv_bfloat16 h = __float2bfloat16(v);
    hi[i] = h;
    lo[i] = __float2bfloat16(v - __bfloat162float(h));
}

// ---------------- mma.sync split-bf16 GEMM, 2-stage cp.async pipeline ---------------
// afp32 = 1: A is fp32 [K][Mg] (w_up); register-prefetched + converted in-kernel
// mode 0: fused upsample-combine epilogue -> cond_raw^T hi/lo [1016][2048]
// mode 1: +bias, write hi/lo transposed [n][2048] at col bm
// mode 2: +bias, write fp32 [m][1016]
__global__ __launch_bounds__(256)
void k_gemm_tc(const __nv_bfloat16* __restrict__ Ahi, const __nv_bfloat16* __restrict__ Alo,
               const float* __restrict__ Af32, int Mg, int afp32,
               const __nv_bfloat16* __restrict__ Bhi, const __nv_bfloat16* __restrict__ Blo,
               int K, int mode, const float* __restrict__ bias,
               float* __restrict__ outF,
               __nv_bfloat16* __restrict__ outHi, __nv_bfloat16* __restrict__ outLo)
{
    extern __shared__ char smem[];
    uint32_t sb = s2u(smem);
    const int tid = threadIdx.x;
    const int wid = tid >> 5, lane = tid & 31;
    const int bm = blockIdx.x * 128, bn = blockIdx.y * 128;
    const int wm = (wid >> 1) * 32, wn = (wid & 1) * 64;

    const uint32_t STG = 32768;  // per-stage bytes: A_HI 0, A_LO 8192, B_HI 16384, B_LO 24576

    float acc[2][8][4];
#pragma unroll
    for (int mt = 0; mt < 2; mt++)
#pragma unroll
        for (int nt = 0; nt < 8; nt++)
#pragma unroll
            for (int i = 0; i < 4; i++) acc[mt][nt][i] = 0.0f;

    float4 pre[4];
    const int nsteps = K >> 5;

    // ---- prologue: fill stage 0 ----
    if (afp32) {
#pragma unroll
        for (int i = 0; i < 4; i++) {
            int u = tid + i * 256;
            int k = u >> 5, f4 = u & 31;
            pre[i] = *reinterpret_cast<const float4*>(Af32 + (size_t)k * Mg + bm + f4 * 4);
        }
#pragma unroll
        for (int i = 0; i < 4; i++) {
            int u = tid + i * 256;
            int k = u >> 5, f4 = u & 31;
            float4 v = pre[i];
            __nv_bfloat16 h0 = __float2bfloat16(v.x), h1 = __float2bfloat16(v.y);
            __nv_bfloat16 h2 = __float2bfloat16(v.z), h3 = __float2bfloat16(v.w);
            uint32_t hi01 = (uint32_t)__bfloat16_as_ushort(h0) |
                            ((uint32_t)__bfloat16_as_ushort(h1) << 16);
            uint32_t hi23 = (uint32_t)__bfloat16_as_ushort(h2) |
                            ((uint32_t)__bfloat16_as_ushort(h3) << 16);
            uint32_t lo01 = bpack(v.x - __bfloat162float(h0), v.y - __bfloat162float(h1));
            uint32_t lo23 = bpack(v.z - __bfloat162float(h2), v.w - __bfloat162float(h3));
            int mc = f4 >> 1, half = f4 & 1;
            uint32_t a = off_tr(k, mc) + half * 8;
            *reinterpret_cast<uint2*>(smem + a) = make_uint2(hi01, hi23);
            *reinterpret_cast<uint2*>(smem + 8192 + a) = make_uint2(lo01, lo23);
        }
#pragma unroll
        for (int i = 0; i < 2; i++) {
            int idx = tid + i * 256;
            int row = idx >> 2, kk = idx & 3;
            uint32_t d = off_km(row, kk);
            cp16(sb + 16384 + d, Bhi + (size_t)(bn + row) * K + kk * 8);
            cp16(sb + 24576 + d, Blo + (size_t)(bn + row) * K + kk * 8);
        }
    } else {
#pragma unroll
        for (int i = 0; i < 2; i++) {
            int idx = tid + i * 256;
            int row = idx >> 2, kk = idx & 3;
            uint32_t d = off_km(row, kk);
            cp16(sb + d,         Ahi + (size_t)(bm + row) * K + kk * 8);
            cp16(sb + 8192 + d,  Alo + (size_t)(bm + row) * K + kk * 8);
            cp16(sb + 16384 + d, Bhi + (size_t)(bn + row) * K + kk * 8);
            cp16(sb + 24576 + d, Blo + (size_t)(bn + row) * K + kk * 8);
        }
    }
    CP_COMMIT();

    for (int it = 0; it < nsteps; it++) {
        const int b = it & 1, nb = b ^ 1;
        const bool more = (it + 1 < nsteps);
        const int k1 = (it + 1) * 32;
        uint32_t nbase = sb + nb * STG;

        if (more) {
            if (afp32) {
#pragma unroll
                for (int i = 0; i < 4; i++) {
                    int u = tid + i * 256;
                    int k = u >> 5, f4 = u & 31;
                    pre[i] = *reinterpret_cast<const float4*>(
                        Af32 + (size_t)(k1 + k) * Mg + bm + f4 * 4);
                }
#pragma unroll
                for (int i = 0; i < 2; i++) {
                    int idx = tid + i * 256;
                    int row = idx >> 2, kk = idx & 3;
                    uint32_t d = off_km(row, kk);
                    cp16(nbase + 16384 + d, Bhi + (size_t)(bn + row) * K + k1 + kk * 8);
                    cp16(nbase + 24576 + d, Blo + (size_t)(bn + row) * K + k1 + kk * 8);
                }
            } else {
#pragma unroll
                for (int i = 0; i < 2; i++) {
                    int idx = tid + i * 256;
                    int row = idx >> 2, kk = idx & 3;
                    uint32_t d = off_km(row, kk);
                    cp16(nbase + d,         Ahi + (size_t)(bm + row) * K + k1 + kk * 8);
                    cp16(nbase + 8192 + d,  Alo + (size_t)(bm + row) * K + k1 + kk * 8);
                    cp16(nbase + 16384 + d, Bhi + (size_t)(bn + row) * K + k1 + kk * 8);
                    cp16(nbase + 24576 + d, Blo + (size_t)(bn + row) * K + k1 + kk * 8);
                }
            }
            CP_COMMIT();
            asm volatile("cp.async.wait_group 1;" ::: "memory");
        } else {
            asm volatile("cp.async.wait_group 0;" ::: "memory");
        }
        __syncthreads();

        // ---- compute stage b ----
        uint32_t base = sb + b * STG;
#pragma unroll
        for (int s = 0; s < 2; s++) {
            const int kk0 = s * 2;
            uint32_t af[2][2][4];
#pragma unroll
            for (int mt = 0; mt < 2; mt++) {
                if (afp32) {
                    int k  = s * 16 + ((lane >> 4) << 3) + (lane & 7);
                    int mc = ((wm + mt * 16) >> 3) + ((lane >> 3) & 1);
                    uint32_t ad = off_tr(k, mc);
                    ldsm4t(af[mt][0], base + ad);
                    ldsm4t(af[mt][1], base + 8192 + ad);
                } else {
                    int row = wm + mt * 16 + (lane & 15);
                    int kk  = kk0 + (lane >> 4);
                    uint32_t ad = off_km(row, kk);
                    ldsm4(af[mt][0], base + ad);
                    ldsm4(af[mt][1], base + 8192 + ad);
                }
            }
            uint32_t bh[8][2], bl[8][2];
#pragma unroll
            for (int p = 0; p < 4; p++) {
                int nb2 = wn + p * 16;
                int row = nb2 + ((lane >> 4) << 3) + (lane & 7);
                int kk  = kk0 + ((lane >> 3) & 1);
                uint32_t bd = off_km(row, kk);
                uint32_t r[4];
                ldsm4(r, base + 16384 + bd);
                bh[2 * p][0] = r[0]; bh[2 * p][1] = r[1];
                bh[2 * p + 1][0] = r[2]; bh[2 * p + 1][1] = r[3];
                ldsm4(r, base + 24576 + bd);
                bl[2 * p][0] = r[0]; bl[2 * p][1] = r[1];
                bl[2 * p + 1][0] = r[2]; bl[2 * p + 1][1] = r[3];
            }
#pragma unroll
            for (int mt = 0; mt < 2; mt++)
#pragma unroll
                for (int nt = 0; nt < 8; nt++) {
                    mma_bf16(acc[mt][nt], af[mt][0], bh[nt]);
                    mma_bf16(acc[mt][nt], af[mt][0], bl[nt]);
                    mma_bf16(acc[mt][nt], af[mt][1], bh[nt]);
                }
        }
        __syncthreads();

        // deferred A convert into next stage (after compute done)
        if (afp32 && more) {
#pragma unroll
            for (int i = 0; i < 4; i++) {
                int u = tid + i * 256;
                int k = u >> 5, f4 = u & 31;
                float4 v = pre[i];
                __nv_bfloat16 h0 = __float2bfloat16(v.x), h1 = __float2bfloat16(v.y);
                __nv_bfloat16 h2 = __float2bfloat16(v.z), h3 = __float2bfloat16(v.w);
                uint32_t hi01 = (uint32_t)__bfloat16_as_ushort(h0) |
                                ((uint32_t)__bfloat16_as_ushort(h1) << 16);
                uint32_t hi23 = (uint32_t)__bfloat16_as_ushort(h2) |
                                ((uint32_t)__bfloat16_as_ushort(h3) << 16);
                uint32_t lo01 = bpack(v.x - __bfloat162float(h0), v.y - __bfloat162float(h1));
                uint32_t lo23 = bpack(v.z - __bfloat162float(h2), v.w - __bfloat162float(h3));
                int mc = f4 >> 1, half = f4 & 1;
                uint32_t a = off_tr(k, mc) + half * 8;
                *reinterpret_cast<uint2*>(smem + nb * STG + a) = make_uint2(hi01, hi23);
                *reinterpret_cast<uint2*>(smem + nb * STG + 8192 + a) = make_uint2(lo01, lo23);
            }
        }
    }
    __syncthreads();

    // ---- stage D (128x128) to smem, stride 129 ----
    float* sd = reinterpret_cast<float*>(smem);
#pragma unroll
    for (int mt = 0; mt < 2; mt++)
#pragma unroll
        for (int nt = 0; nt < 8; nt++) {
            int r = wm + mt * 16 + (lane >> 2);
            int c = wn + nt * 8 + (lane & 3) * 2;
            sd[r * 129 + c]           = acc[mt][nt][0];
            sd[r * 129 + c + 1]       = acc[mt][nt][1];
            sd[(r + 8) * 129 + c]     = acc[mt][nt][2];
            sd[(r + 8) * 129 + c + 1] = acc[mt][nt][3];
        }
    __syncthreads();

    if (mode == 0) {
        int bo = bm >> 4;
        for (int u = tid; u < T_LEN; u += 256) {
            int m = u >> 3, p = u & 7;
            uint4 vh, vl;
            __nv_bfloat16* hp = (__nv_bfloat16*)&vh;
            __nv_bfloat16* lp = (__nv_bfloat16*)&vl;
#pragma unroll
            for (int ol = 0; ol < 8; ol++) {
                float v = sd[(ol * 16 + p + 8) * 129 + m] +
                          sd[(ol * 16 + p) * 129 + m + 1] + bias[bo + ol];
                __nv_bfloat16 h = __float2bfloat16(v);
                hp[ol] = h;
                lp[ol] = __float2bfloat16(v - __bfloat162float(h));
            }
            *reinterpret_cast<uint4*>(outHi + (size_t)u * 2048 + bo) = vh;
            *reinterpret_cast<uint4*>(outLo + (size_t)u * 2048 + bo) = vl;
        }
    } else if (mode == 1) {
        int mg = (tid & 31) * 4;
        int nl = tid >> 5;
        for (int n0 = 0; n0 < 128; n0 += 8) {
            int n = n0 + nl;
            uint2 vh, vl;
            __nv_bfloat16* hp = (__nv_bfloat16*)&vh;
            __nv_bfloat16* lp = (__nv_bfloat16*)&vl;
#pragma unroll
            for (int j = 0; j < 4; j++) {
                float v = sd[(mg + j) * 129 + n] + bias[bm + mg + j];
                __nv_bfloat16 h = __float2bfloat16(v);
                hp[j] = h;
                lp[j] = __float2bfloat16(v - __bfloat162float(h));
            }
            *reinterpret_cast<uint2*>(outHi + (size_t)(bn + n) * 2048 + bm + mg) = vh;
            *reinterpret_cast<uint2*>(outLo + (size_t)(bn + n) * 2048 + bm + mg) = vl;
        }
    } else {
        int mo = tid >> 7, n = tid & 127;
        int gn = bn + n;
        if (gn < T_LEN) {
            for (int m0 = 0; m0 < 128; m0 += 2) {
                int m = m0 + mo;
                outF[(size_t)(bm + m) * T_LEN + gn] = sd[m * 129 + n] + bias[bm + m];
            }
        }
    }
}

// ---------------- one full WaveNet layer (dil conv + gate + res + skip) --------------
__global__ __launch_bounds__(128)
void k_layer(const float* __restrict__ w_dil_all, const float* __restrict__ b_dil_all,
             const float* __restrict__ b_res_all, const float* __restrict__ b_skip_all,
             int layer)
{
    __shared__ float xs0[64][LT];
    __shared__ float xs1[64][LT];
    __shared__ float ws[32][128];
    __shared__ float ia_hi[64][LT];
    __shared__ float acts[64][LT];

    const int d = 1 << (layer & 7);
    const float* xin  = g_scratch + ((layer & 1) ? OFF_X1 : OFF_X0);
    float*       xout = g_scratch + ((layer & 1) ? OFF_X0 : OFF_X1);
    const float* cond = g_scratch + OFF_CACTS + (size_t)layer * 128 * T_LEN;
    float*       skip = g_scratch + OFF_SKIP;
    const float* w_dil  = w_dil_all  + (size_t)layer * 128 * 64 * 2;
    const float* b_dil  = b_dil_all  + layer * 128;
    const float* wskT   = g_scratch + OFF_WSKT + (size_t)layer * 64 * 256;
    const float* wrsT   = g_scratch + OFF_WRST + (size_t)layer * 64 * 64;
    const float* b_skip = b_skip_all + layer * 256;

    int t0 = blockIdx.x * LT;
    int c  = threadIdx.x;

    for (int idx = c; idx < 64 * LT; idx += 128) {
        int j = idx / LT, tt = idx % LT;
        int ta = t0 - d + tt;
        xs0[j][tt] = (ta >= 0 && ta < T_LEN) ? xin[(size_t)j * T_LEN + ta] : 0.0f;
        int tb = t0 + tt;
        xs1[j][tt] = (tb < T_LEN) ? xin[(size_t)j * T_LEN + tb] : 0.0f;
    }

    float acc[LT];
#pragma unroll
    for (int tt = 0; tt < LT; tt++) acc[tt] = 0.0f;

    for (int jc = 0; jc < 64; jc += 16) {
        __syncthreads();
        for (int idx = c; idx < 16 * 128 * 2; idx += 128) {
            int cc = idx >> 5;
            int r  = idx & 31;
            ws[r][cc] = w_dil[cc * 128 + jc * 2 + r];
        }
        __syncthreads();
#pragma unroll
        for (int jj = 0; jj < 16; jj++) {
            float w0 = ws[2 * jj][c];
            float w1 = ws[2 * jj + 1][c];
            const float4* p0 = (const float4*)&xs0[jc + jj][0];
            const float4* p1 = (const float4*)&xs1[jc + jj][0];
#pragma unroll
            for (int v = 0; v < 4; v++) {
                float4 a = p0[v]; float4 b = p1[v];
                acc[v * 4 + 0] += w0 * a.x + w1 * b.x;
                acc[v * 4 + 1] += w0 * a.y + w1 * b.y;
                acc[v * 4 + 2] += w0 * a.z + w1 * b.z;
                acc[v * 4 + 3] += w0 * a.w + w1 * b.w;
            }
        }
    }

    {
        float bd = b_dil[c];
#pragma unroll
        for (int tt = 0; tt < LT; tt++) {
            int t = t0 + tt;
            float cv = (t < T_LEN) ? cond[(size_t)c * T_LEN + t] : 0.0f;
            acc[tt] += bd + cv;
        }
    }
    __syncthreads();
    if (c >= 64) {
#pragma unroll
        for (int tt = 0; tt < LT; tt++) ia_hi[c - 64][tt] = acc[tt];
    }
    __syncthreads();
    if (c < 64) {
#pragma unroll
        for (int tt = 0; tt < LT; tt++) {
            float g  = ia_hi[c][tt];
            float sg = 1.0f / (1.0f + expf(-g));
            acts[c][tt] = tanhf(acc[tt]) * sg;
        }
    }
    __syncthreads();

    if (layer < 15 && c < 64) {
        float r[LT];
#pragma unroll
        for (int tt = 0; tt < LT; tt++) r[tt] = 0.0f;
        for (int k = 0; k < 64; k++) {
            float w = wrsT[k * 64 + c];
            const float4* ap = (const float4*)&acts[k][0];
#pragma unroll
            for (int v = 0; v < 4; v++) {
                float4 a = ap[v];
                r[v * 4 + 0] += w * a.x; r[v * 4 + 1] += w * a.y;
                r[v * 4 + 2] += w * a.z; r[v * 4 + 3] += w * a.w;
            }
        }
        float br = b_res_all[layer * 64 + c];
#pragma unroll
        for (int tt = 0; tt < LT; tt++) {
            int t = t0 + tt;
            if (t < T_LEN)
                xout[(size_t)c * T_LEN + t] = xin[(size_t)c * T_LEN + t] + r[tt] + br;
        }
    }

#pragma unroll
    for (int rr = 0; rr < 2; rr++) {
        int row = c + rr * 128;
        float s[LT];
#pragma unroll
        for (int tt = 0; tt < LT; tt++) s[tt] = 0.0f;
        for (int k = 0; k < 64; k++) {
            float w = wskT[k * 256 + row];
            const float4* ap = (const float4*)&acts[k][0];
#pragma unroll
            for (int v = 0; v < 4; v++) {
                float4 a = ap[v];
                s[v * 4 + 0] += w * a.x; s[v * 4 + 1] += w * a.y;
                s[v * 4 + 2] += w * a.z; s[v * 4 + 3] += w * a.w;
            }
        }
        float bs = b_skip[row];
#pragma unroll
        for (int tt = 0; tt < LT; tt++) {
            int t = t0 + tt;
            if (t < T_LEN) {
                size_t oidx = (size_t)row * T_LEN + t;
                float v = s[tt] + bs;
                skip[oidx] = (layer == 0) ? v : (skip[oidx] + v);
            }
        }
    }
}

// ---------------- head GEMM (256x256), optional relu / shifted store -----------------
__global__ __launch_bounds__(256)
void k_head(const float* __restrict__ in, const float* __restrict__ wT,
            float* __restrict__ out, int relu_in, int relu_out, int shifted)
{
    __shared__ float hs[256 * HT];
    int t0 = blockIdx.x * HT;
    int o  = threadIdx.x;
    for (int idx = o; idx < 256 * HT; idx += 256) {
        int cc = idx / HT, tt = idx % HT;
        int t = t0 + tt;
        float v = (t < T_LEN) ? in[(size_t)cc * T_LEN + t] : 0.0f;
        if (relu_in) v = fmaxf(v, 0.0f);
        hs[idx] = v;
    }
    __syncthreads();
    float acc[HT];
#pragma unroll
    for (int tt = 0; tt < HT; tt++) acc[tt] = 0.0f;
    for (int cc = 0; cc < 256; cc++) {
        float w = wT[cc * 256 + o];
        const float4* h4 = (const float4*)&hs[cc * HT];
#pragma unroll
        for (int v = 0; v < 4; v++) {
            float4 h = h4[v];
            acc[v * 4 + 0] += w * h.x; acc[v * 4 + 1] += w * h.y;
            acc[v * 4 + 2] += w * h.z; acc[v * 4 + 3] += w * h.w;
        }
    }
    if (shifted) {
        if (blockIdx.x == 0) out[(size_t)o * T_LEN] = 0.0f;
#pragma unroll
        for (int tt = 0; tt < HT; tt++) {
            int t = t0 + tt;
            if (t + 1 < T_LEN) out[(size_t)o * T_LEN + t + 1] = acc[tt];
        }
    } else {
#pragma unroll
        for (int tt = 0; tt < HT; tt++) {
            int t = t0 + tt;
            if (t < T_LEN) {
                float v = acc[tt];
                if (relu_out) v = fmaxf(v, 0.0f);
                out[(size_t)o * T_LEN + t] = v;
            }
        }
    }
}

// ---------------- launch -------------------------------------------------------------
extern "C" void kernel_launch(void* const* d_in, const int* in_sizes, int n_in,
                              void* d_out, int out_size)
{
    const float* features = (const float*)d_in[0];
    const float* audio    = (const float*)d_in[1];
    const float* w_up     = (const float*)d_in[2];
    const float* b_up     = (const float*)d_in[3];
    const float* w_cond   = (const float*)d_in[4];
    const float* b_cond   = (const float*)d_in[5];
    const float* embed    = (const float*)d_in[6];
    const float* w_dil    = (const float*)d_in[7];
    const float* b_dil    = (const float*)d_in[8];
    const float* w_res    = (const float*)d_in[9];
    const float* b_res    = (const float*)d_in[10];
    const float* w_skip   = (const float*)d_in[11];
    const float* b_skip   = (const float*)d_in[12];
    const float* w_out    = (const float*)d_in[13];
    const float* w_end    = (const float*)d_in[14];
    float* out = (float*)d_out;

    float* scr = nullptr;
    cudaGetSymbolAddress((void**)&scr, g_scratch);

    __nv_bfloat16* WC_HI = (__nv_bfloat16*)(scr + OFF_WC_HI);
    __nv_bfloat16* WC_LO = (__nv_bfloat16*)(scr + OFF_WC_LO);
    __nv_bfloat16* FT_HI = (__nv_bfloat16*)(scr + OFF_FT_HI);
    __nv_bfloat16* FT_LO = (__nv_bfloat16*)(scr + OFF_FT_LO);
    __nv_bfloat16* BR_HI = (__nv_bfloat16*)(scr + OFF_BR_HI);
    __nv_bfloat16* BR_LO = (__nv_bfloat16*)(scr + OFF_BR_LO);
    __nv_bfloat16* B2_HI = (__nv_bfloat16*)(scr + OFF_B2_HI);
    __nv_bfloat16* B2_LO = (__nv_bfloat16*)(scr + OFF_B2_LO);

    cudaFuncSetAttribute(k_gemm_tc, cudaFuncAttributeMaxDynamicSharedMemorySize, 67584);

    int write_q = (out_size >= 256 * T_LEN + T_LEN) ? 1 : 0;

    dim3 tb(32, 8);
    // launches 1-5 (ncu -s 5 skips these; #6 = upsample GEMM gets profiled)
    k_encode<<<(T_LEN + 255) / 256, 256>>>(audio, out + (size_t)256 * T_LEN, write_q);
    k_embed<<<(64 * T_LEN + 255) / 256, 256>>>(embed);
    k_tsplit<<<dim3(4, 64), tb>>>(features, FT_HI, FT_LO, 2048, 128);
    k_split<<<(2048 * 2048) / 256, 256>>>(w_cond, WC_HI, WC_LO, 2048 * 2048);
    k_transpose_b<<<dim3(2, 8, 16), tb>>>(w_skip, scr + OFF_WSKT, 256, 64,
                                          256 * 64, 64 * 256);

    // #6: upsample GEMM (A = w_up fp32 direct) + fused combine -> cond_raw^T hi/lo
    k_gemm_tc<<<dim3(256, 1), 256, 67584>>>(nullptr, nullptr, w_up, 32768, 1,
                                            FT_HI, FT_LO, 2048, 0,
                                            b_up, nullptr, BR_HI, BR_LO);
    // cond GEMM #1 -> cond1^T hi/lo
    k_gemm_tc<<<dim3(16, 8), 256, 67584>>>(WC_HI, WC_LO, nullptr, 0, 0,
                                           BR_HI, BR_LO, 2048, 1,
                                           b_cond, nullptr, B2_HI, B2_LO);
    // cond GEMM #2 -> cond_acts fp32 [2048][1016]
    k_gemm_tc<<<dim3(16, 8), 256, 67584>>>(WC_HI, WC_LO, nullptr, 0, 0,
                                           B2_HI, B2_LO, 2048, 2,
                                           b_cond, scr + OFF_CACTS, nullptr, nullptr);

    k_transpose_b<<<dim3(2, 2, 15), tb>>>(w_res, scr + OFF_WRST, 64, 64,
                                          64 * 64, 64 * 64);
    k_transpose<<<dim3(8, 8), tb>>>(w_out, scr + OFF_WOT, 256, 256);
    k_transpose<<<dim3(8, 8), tb>>>(w_end, scr + OFF_WET, 256, 256);

    int lblocks = (T_LEN + LT - 1) / LT;
    for (int i = 0; i < 16; i++)
        k_layer<<<lblocks, 128>>>(w_dil, b_dil, b_res, b_skip, i);

    int hblocks = (T_LEN + HT - 1) / HT;
    k_head<<<hblocks, 256>>>(scr + OFF_SKIP, scr + OFF_WOT, scr + OFF_H1, 1, 1, 0);
    k_head<<<hblocks, 256>>>(scr + OFF_H1, scr + OFF_WET, out, 0, 0, 1);
}

// round 5
// speedup vs baseline: 2.2642x; 1.4916x over previous
#include <cuda_runtime.h>
#include <cuda_bf16.h>
#include <math.h>
#include <stdint.h>

#define T_LEN 1016
#define TB 8          // time-steps per block in the fused tail kernel (127*8 = 1016)
#define NBLK 127

// ---------------- scratch layout (float units) -------------------------------------
constexpr size_t OFF_WC_HI  = 0;                                  // bf16[2048*2048]
constexpr size_t OFF_WC_LO  = OFF_WC_HI  + 2097152;
constexpr size_t OFF_FT_HI  = OFF_WC_LO  + 2097152;               // bf16[128*2048]
constexpr size_t OFF_FT_LO  = OFF_FT_HI  + 131072;
constexpr size_t OFF_BR_HI  = OFF_FT_LO  + 131072;                // bf16[1024*2048]
constexpr size_t OFF_BR_LO  = OFF_BR_HI  + 1048576;
constexpr size_t OFF_B2_HI  = OFF_BR_LO  + 1048576;               // bf16[1024*2048]
constexpr size_t OFF_B2_LO  = OFF_B2_HI  + 1048576;
constexpr size_t OFF_CACTS  = OFF_B2_LO  + 1048576;               // f32[2048*1016]
constexpr size_t OFF_WOT    = OFF_CACTS  + 2080768;
constexpr size_t OFF_WET    = OFF_WOT    + 65536;
constexpr size_t OFF_X0     = OFF_WET    + 65536;
constexpr size_t OFF_X1     = OFF_X0     + 65024;
constexpr size_t OFF_Q      = OFF_X1     + 65024;
constexpr size_t OFF_WSKT   = OFF_Q      + 1024;                  // f32[16][64][256]
constexpr size_t OFF_WRST   = OFF_WSKT   + 262144;                // f32[15][64][64]
constexpr size_t SCRATCH_SZ = OFF_WRST + 61440;

__device__ __align__(1024) float g_scratch[SCRATCH_SZ];
__device__ unsigned g_bar;

// ---------------- PTX helpers -------------------------------------------------------
__device__ __forceinline__ uint32_t s2u(const void* p) {
    uint32_t a;
    asm("{ .reg .u64 t; cvta.to.shared.u64 t, %1; cvt.u32.u64 %0, t; }" : "=r"(a) : "l"(p));
    return a;
}
__device__ __forceinline__ void cp16(uint32_t dst, const void* src) {
    asm volatile("cp.async.cg.shared.global [%0], [%1], 16;" :: "r"(dst), "l"(src));
}
#define CP_COMMIT() asm volatile("cp.async.commit_group;" ::: "memory")

__device__ __forceinline__ void ldsm4(uint32_t* r, uint32_t a) {
    asm volatile("ldmatrix.sync.aligned.m8n8.x4.shared.b16 {%0,%1,%2,%3}, [%4];"
                 : "=r"(r[0]), "=r"(r[1]), "=r"(r[2]), "=r"(r[3]) : "r"(a));
}
__device__ __forceinline__ void ldsm4t(uint32_t* r, uint32_t a) {
    asm volatile("ldmatrix.sync.aligned.m8n8.x4.trans.shared.b16 {%0,%1,%2,%3}, [%4];"
                 : "=r"(r[0]), "=r"(r[1]), "=r"(r[2]), "=r"(r[3]) : "r"(a));
}
__device__ __forceinline__ void mma_bf16(float* c, const uint32_t* a, const uint32_t* b) {
    asm volatile("mma.sync.aligned.m16n8k16.row.col.f32.bf16.bf16.f32 "
                 "{%0,%1,%2,%3}, {%4,%5,%6,%7}, {%8,%9}, {%0,%1,%2,%3};"
                 : "+f"(c[0]), "+f"(c[1]), "+f"(c[2]), "+f"(c[3])
                 : "r"(a[0]), "r"(a[1]), "r"(a[2]), "r"(a[3]), "r"(b[0]), "r"(b[1]));
}

__device__ __forceinline__ uint32_t off_km(int row, int kk) {
    return (uint32_t)(row * 64 + ((kk ^ ((row >> 1) & 3)) << 4));
}
__device__ __forceinline__ uint32_t off_tr(int k, int mc) {
    return (uint32_t)(k * 256 + ((mc ^ (k & 7)) << 4));
}
__device__ __forceinline__ uint32_t bpack(float x, float y) {
    uint32_t lo = (uint32_t)__bfloat16_as_ushort(__float2bfloat16(x));
    uint32_t hi = (uint32_t)__bfloat16_as_ushort(__float2bfloat16(y));
    return lo | (hi << 16);
}

// ---------------- transpose fp32 (R x C -> C x R) -----------------------------------
__global__ void k_transpose(const float* __restrict__ in, float* __restrict__ out,
                            int R, int C)
{
    __shared__ float tile[32][33];
    int c0 = blockIdx.x * 32, r0 = blockIdx.y * 32;
    int x = threadIdx.x, y = threadIdx.y;
#pragma unroll
    for (int i = 0; i < 32; i += 8)
        tile[y + i][x] = in[(size_t)(r0 + y + i) * C + c0 + x];
    __syncthreads();
#pragma unroll
    for (int i = 0; i < 32; i += 8)
        out[(size_t)(c0 + y + i) * R + r0 + x] = tile[x][y + i];
}

__global__ void k_transpose_b(const float* __restrict__ in, float* __restrict__ out,
                              int R, int C, size_t inL, size_t outL)
{
    __shared__ float tile[32][33];
    int l = blockIdx.z;
    const float* ip = in + (size_t)l * inL;
    float* op = out + (size_t)l * outL;
    int c0 = blockIdx.x * 32, r0 = blockIdx.y * 32;
    int x = threadIdx.x, y = threadIdx.y;
#pragma unroll
    for (int i = 0; i < 32; i += 8)
        tile[y + i][x] = ip[(size_t)(r0 + y + i) * C + c0 + x];
    __syncthreads();
#pragma unroll
    for (int i = 0; i < 32; i += 8)
        op[(size_t)(c0 + y + i) * R + r0 + x] = tile[x][y + i];
}

// ---------------- transpose + bf16 hi/lo split: in[R][C] -> out[C][R] ----------------
__global__ void k_tsplit(const float* __restrict__ in, __nv_bfloat16* __restrict__ hi,
                         __nv_bfloat16* __restrict__ lo, int R, int C)
{
    __shared__ float tile[32][33];
    int c0 = blockIdx.x * 32, r0 = blockIdx.y * 32;
    int x = threadIdx.x, y = threadIdx.y;
#pragma unroll
    for (int i = 0; i < 32; i += 8)
        tile[y + i][x] = in[(size_t)(r0 + y + i) * C + c0 + x];
    __syncthreads();
#pragma unroll
    for (int i = 0; i < 32; i += 8) {
        float v = tile[x][y + i];
        size_t o = (size_t)(c0 + y + i) * R + r0 + x;
        __nv_bfloat16 h = __float2bfloat16(v);
        hi[o] = h;
        lo[o] = __float2bfloat16(v - __bfloat162float(h));
    }
}

__global__ void k_split(const float* __restrict__ in, __nv_bfloat16* __restrict__ hi,
                        __nv_bfloat16* __restrict__ lo, int n)
{
    int i = blockIdx.x * 256 + threadIdx.x;
    if (i >= n) return;
    float v = in[i];
    __nv_bfloat16 h = __float2bfloat16(v);
    hi[i] = h;
    lo[i] = __float2bfloat16(v - __bfloat162float(h));
}

// ---------------- mma.sync split-bf16 GEMM, 2-stage cp.async pipeline ---------------
__global__ __launch_bounds__(256)
void k_gemm_tc(const __nv_bfloat16* __restrict__ Ahi, const __nv_bfloat16* __restrict__ Alo,
               const float* __restrict__ Af32, int Mg, int afp32,
               const __nv_bfloat16* __restrict__ Bhi, const __nv_bfloat16* __restrict__ Blo,
               int K, int mode, const float* __restrict__ bias,
               float* __restrict__ outF,
               __nv_bfloat16* __restrict__ outHi, __nv_bfloat16* __restrict__ outLo)
{
    extern __shared__ char smem[];
    uint32_t sb = s2u(smem);
    const int tid = threadIdx.x;
    const int wid = tid >> 5, lane = tid & 31;
    const int bm = blockIdx.x * 128, bn = blockIdx.y * 128;
    const int wm = (wid >> 1) * 32, wn = (wid & 1) * 64;

    const uint32_t STG = 32768;

    float acc[2][8][4];
#pragma unroll
    for (int mt = 0; mt < 2; mt++)
#pragma unroll
        for (int nt = 0; nt < 8; nt++)
#pragma unroll
            for (int i = 0; i < 4; i++) acc[mt][nt][i] = 0.0f;

    float4 pre[4];
    const int nsteps = K >> 5;

    if (afp32) {
#pragma unroll
        for (int i = 0; i < 4; i++) {
            int u = tid + i * 256;
            int k = u >> 5, f4 = u & 31;
            pre[i] = *reinterpret_cast<const float4*>(Af32 + (size_t)k * Mg + bm + f4 * 4);
        }
#pragma unroll
        for (int i = 0; i < 4; i++) {
            int u = tid + i * 256;
            int k = u >> 5, f4 = u & 31;
            float4 v = pre[i];
            __nv_bfloat16 h0 = __float2bfloat16(v.x), h1 = __float2bfloat16(v.y);
            __nv_bfloat16 h2 = __float2bfloat16(v.z), h3 = __float2bfloat16(v.w);
            uint32_t hi01 = (uint32_t)__bfloat16_as_ushort(h0) |
                            ((uint32_t)__bfloat16_as_ushort(h1) << 16);
            uint32_t hi23 = (uint32_t)__bfloat16_as_ushort(h2) |
                            ((uint32_t)__bfloat16_as_ushort(h3) << 16);
            uint32_t lo01 = bpack(v.x - __bfloat162float(h0), v.y - __bfloat162float(h1));
            uint32_t lo23 = bpack(v.z - __bfloat162float(h2), v.w - __bfloat162float(h3));
            int mc = f4 >> 1, half = f4 & 1;
            uint32_t a = off_tr(k, mc) + half * 8;
            *reinterpret_cast<uint2*>(smem + a) = make_uint2(hi01, hi23);
            *reinterpret_cast<uint2*>(smem + 8192 + a) = make_uint2(lo01, lo23);
        }
#pragma unroll
        for (int i = 0; i < 2; i++) {
            int idx = tid + i * 256;
            int row = idx >> 2, kk = idx & 3;
            uint32_t d = off_km(row, kk);
            cp16(sb + 16384 + d, Bhi + (size_t)(bn + row) * K + kk * 8);
            cp16(sb + 24576 + d, Blo + (size_t)(bn + row) * K + kk * 8);
        }
    } else {
#pragma unroll
        for (int i = 0; i < 2; i++) {
            int idx = tid + i * 256;
            int row = idx >> 2, kk = idx & 3;
            uint32_t d = off_km(row, kk);
            cp16(sb + d,         Ahi + (size_t)(bm + row) * K + kk * 8);
            cp16(sb + 8192 + d,  Alo + (size_t)(bm + row) * K + kk * 8);
            cp16(sb + 16384 + d, Bhi + (size_t)(bn + row) * K + kk * 8);
            cp16(sb + 24576 + d, Blo + (size_t)(bn + row) * K + kk * 8);
        }
    }
    CP_COMMIT();

    for (int it = 0; it < nsteps; it++) {
        const int b = it & 1, nb = b ^ 1;
        const bool more = (it + 1 < nsteps);
        const int k1 = (it + 1) * 32;
        uint32_t nbase = sb + nb * STG;

        if (more) {
            if (afp32) {
#pragma unroll
                for (int i = 0; i < 4; i++) {
                    int u = tid + i * 256;
                    int k = u >> 5, f4 = u & 31;
                    pre[i] = *reinterpret_cast<const float4*>(
                        Af32 + (size_t)(k1 + k) * Mg + bm + f4 * 4);
                }
#pragma unroll
                for (int i = 0; i < 2; i++) {
                    int idx = tid + i * 256;
                    int row = idx >> 2, kk = idx & 3;
                    uint32_t d = off_km(row, kk);
                    cp16(nbase + 16384 + d, Bhi + (size_t)(bn + row) * K + k1 + kk * 8);
                    cp16(nbase + 24576 + d, Blo + (size_t)(bn + row) * K + k1 + kk * 8);
                }
            } else {
#pragma unroll
                for (int i = 0; i < 2; i++) {
                    int idx = tid + i * 256;
                    int row = idx >> 2, kk = idx & 3;
                    uint32_t d = off_km(row, kk);
                    cp16(nbase + d,         Ahi + (size_t)(bm + row) * K + k1 + kk * 8);
                    cp16(nbase + 8192 + d,  Alo + (size_t)(bm + row) * K + k1 + kk * 8);
                    cp16(nbase + 16384 + d, Bhi + (size_t)(bn + row) * K + k1 + kk * 8);
                    cp16(nbase + 24576 + d, Blo + (size_t)(bn + row) * K + k1 + kk * 8);
                }
            }
            CP_COMMIT();
            asm volatile("cp.async.wait_group 1;" ::: "memory");
        } else {
            asm volatile("cp.async.wait_group 0;" ::: "memory");
        }
        __syncthreads();

        uint32_t base = sb + b * STG;
#pragma unroll
        for (int s = 0; s < 2; s++) {
            const int kk0 = s * 2;
            uint32_t af[2][2][4];
#pragma unroll
            for (int mt = 0; mt < 2; mt++) {
                if (afp32) {
                    int k  = s * 16 + ((lane >> 4) << 3) + (lane & 7);
                    int mc = ((wm + mt * 16) >> 3) + ((lane >> 3) & 1);
                    uint32_t ad = off_tr(k, mc);
                    ldsm4t(af[mt][0], base + ad);
                    ldsm4t(af[mt][1], base + 8192 + ad);
                } else {
                    int row = wm + mt * 16 + (lane & 15);
                    int kk  = kk0 + (lane >> 4);
                    uint32_t ad = off_km(row, kk);
                    ldsm4(af[mt][0], base + ad);
                    ldsm4(af[mt][1], base + 8192 + ad);
                }
            }
            uint32_t bh[8][2], bl[8][2];
#pragma unroll
            for (int p = 0; p < 4; p++) {
                int nb2 = wn + p * 16;
                int row = nb2 + ((lane >> 4) << 3) + (lane & 7);
                int kk  = kk0 + ((lane >> 3) & 1);
                uint32_t bd = off_km(row, kk);
                uint32_t r[4];
                ldsm4(r, base + 16384 + bd);
                bh[2 * p][0] = r[0]; bh[2 * p][1] = r[1];
                bh[2 * p + 1][0] = r[2]; bh[2 * p + 1][1] = r[3];
                ldsm4(r, base + 24576 + bd);
                bl[2 * p][0] = r[0]; bl[2 * p][1] = r[1];
                bl[2 * p + 1][0] = r[2]; bl[2 * p + 1][1] = r[3];
            }
#pragma unroll
            for (int mt = 0; mt < 2; mt++)
#pragma unroll
                for (int nt = 0; nt < 8; nt++) {
                    mma_bf16(acc[mt][nt], af[mt][0], bh[nt]);
                    mma_bf16(acc[mt][nt], af[mt][0], bl[nt]);
                    mma_bf16(acc[mt][nt], af[mt][1], bh[nt]);
                }
        }
        __syncthreads();

        if (afp32 && more) {
#pragma unroll
            for (int i = 0; i < 4; i++) {
                int u = tid + i * 256;
                int k = u >> 5, f4 = u & 31;
                float4 v = pre[i];
                __nv_bfloat16 h0 = __float2bfloat16(v.x), h1 = __float2bfloat16(v.y);
                __nv_bfloat16 h2 = __float2bfloat16(v.z), h3 = __float2bfloat16(v.w);
                uint32_t hi01 = (uint32_t)__bfloat16_as_ushort(h0) |
                                ((uint32_t)__bfloat16_as_ushort(h1) << 16);
                uint32_t hi23 = (uint32_t)__bfloat16_as_ushort(h2) |
                                ((uint32_t)__bfloat16_as_ushort(h3) << 16);
                uint32_t lo01 = bpack(v.x - __bfloat162float(h0), v.y - __bfloat162float(h1));
                uint32_t lo23 = bpack(v.z - __bfloat162float(h2), v.w - __bfloat162float(h3));
                int mc = f4 >> 1, half = f4 & 1;
                uint32_t a = off_tr(k, mc) + half * 8;
                *reinterpret_cast<uint2*>(smem + nb * STG + a) = make_uint2(hi01, hi23);
                *reinterpret_cast<uint2*>(smem + nb * STG + 8192 + a) = make_uint2(lo01, lo23);
            }
        }
    }
    __syncthreads();

    float* sd = reinterpret_cast<float*>(smem);
#pragma unroll
    for (int mt = 0; mt < 2; mt++)
#pragma unroll
        for (int nt = 0; nt < 8; nt++) {
            int r = wm + mt * 16 + (lane >> 2);
            int c = wn + nt * 8 + (lane & 3) * 2;
            sd[r * 129 + c]           = acc[mt][nt][0];
            sd[r * 129 + c + 1]       = acc[mt][nt][1];
            sd[(r + 8) * 129 + c]     = acc[mt][nt][2];
            sd[(r + 8) * 129 + c + 1] = acc[mt][nt][3];
        }
    __syncthreads();

    if (mode == 0) {
        int bo = bm >> 4;
        for (int u = tid; u < T_LEN; u += 256) {
            int m = u >> 3, p = u & 7;
            uint4 vh, vl;
            __nv_bfloat16* hp = (__nv_bfloat16*)&vh;
            __nv_bfloat16* lp = (__nv_bfloat16*)&vl;
#pragma unroll
            for (int ol = 0; ol < 8; ol++) {
                float v = sd[(ol * 16 + p + 8) * 129 + m] +
                          sd[(ol * 16 + p) * 129 + m + 1] + bias[bo + ol];
                __nv_bfloat16 h = __float2bfloat16(v);
                hp[ol] = h;
                lp[ol] = __float2bfloat16(v - __bfloat162float(h));
            }
            *reinterpret_cast<uint4*>(outHi + (size_t)u * 2048 + bo) = vh;
            *reinterpret_cast<uint4*>(outLo + (size_t)u * 2048 + bo) = vl;
        }
    } else if (mode == 1) {
        int mg = (tid & 31) * 4;
        int nl = tid >> 5;
        for (int n0 = 0; n0 < 128; n0 += 8) {
            int n = n0 + nl;
            uint2 vh, vl;
            __nv_bfloat16* hp = (__nv_bfloat16*)&vh;
            __nv_bfloat16* lp = (__nv_bfloat16*)&vl;
#pragma unroll
            for (int j = 0; j < 4; j++) {
                float v = sd[(mg + j) * 129 + n] + bias[bm + mg + j];
                __nv_bfloat16 h = __float2bfloat16(v);
                hp[j] = h;
                lp[j] = __float2bfloat16(v - __bfloat162float(h));
            }
            *reinterpret_cast<uint2*>(outHi + (size_t)(bn + n) * 2048 + bm + mg) = vh;
            *reinterpret_cast<uint2*>(outLo + (size_t)(bn + n) * 2048 + bm + mg) = vl;
        }
    } else {
        int mo = tid >> 7, n = tid & 127;
        int gn = bn + n;
        if (gn < T_LEN) {
            for (int m0 = 0; m0 < 128; m0 += 2) {
                int m = m0 + mo;
                outF[(size_t)(bm + m) * T_LEN + gn] = sd[m * 129 + n] + bias[bm + m];
            }
        }
    }
}

// ---------------- barrier reset ------------------------------------------------------
__global__ void k_reset() { g_bar = 0; }

// ---------------- fused persistent tail: encode+embed+16 layers+heads ----------------
__global__ __launch_bounds__(256)
void k_tail(const float* __restrict__ audio, const float* __restrict__ embed,
            const float* __restrict__ w_dil_all, const float* __restrict__ b_dil_all,
            const float* __restrict__ b_res_all, const float* __restrict__ b_skip_all,
            float* __restrict__ out, int write_q)
{
    __shared__ float WD[4096];          // 16j x 2tap x 128c weight chunk
    __shared__ float XS0[64 * TB];
    __shared__ float XS1[64 * TB];
    __shared__ float IA[64 * TB];
    __shared__ float ACT[64 * TB];
    __shared__ float HS[256 * TB];
    __shared__ float HS2[256 * TB];
    __shared__ int QS[TB];

    const int tid = threadIdx.x;
    const int t0 = blockIdx.x * TB;
    unsigned bar_target = 0;

    // ---- mu-law encode (own tile) ----
    if (tid < TB) {
        int t = t0 + tid;
        float x = audio[t];
        float xc = fminf(1.0f, fmaxf(-1.0f, x));
        float s  = (xc > 0.0f) ? 1.0f : ((xc < 0.0f) ? -1.0f : 0.0f);
        float num = log1pf(__fmul_rn(255.0f, fabsf(xc)));
        float den = log1pf(255.0f);
        float m = __fdiv_rn(__fmul_rn(s, num), den);
        float v = __fadd_rn(__fmul_rn(__fmul_rn(__fadd_rn(m, 1.0f), 0.5f), 255.0f), 0.5f);
        v = fminf(255.0f, fmaxf(0.0f, v));
        int q = (int)v;
        QS[tid] = q;
        if (write_q) out[(size_t)256 * T_LEN + t] = (float)q;
    }
    __syncthreads();

    // ---- embedding -> X0 ----
    {
        float* X0 = g_scratch + OFF_X0;
        for (int idx = tid; idx < 64 * TB; idx += 256) {
            int j = idx / TB, tt = idx % TB;
            X0[(size_t)j * T_LEN + t0 + tt] = embed[QS[tt] * 64 + j];
        }
    }

    // grid barrier helper
    auto gbar = [&]() {
        bar_target += NBLK;
        __syncthreads();
        __threadfence();
        if (tid == 0) {
            atomicAdd(&g_bar, 1u);
            unsigned v;
            do {
                asm volatile("ld.global.acquire.gpu.u32 %0, [%1];"
                             : "=r"(v) : "l"(&g_bar) : "memory");
            } while (v < bar_target);
        }
        __syncthreads();
    };
    gbar();   // X0 complete grid-wide

    float s_acc[TB];
#pragma unroll
    for (int tt = 0; tt < TB; tt++) s_acc[tt] = 0.0f;

    const int c  = tid & 127;
    const int th = tid >> 7;       // 2 halves x 4 t

    for (int layer = 0; layer < 16; layer++) {
        const int d = 1 << (layer & 7);
        const float* xin  = g_scratch + ((layer & 1) ? OFF_X1 : OFF_X0);
        float*       xout = g_scratch + ((layer & 1) ? OFF_X0 : OFF_X1);
        const float* cond = g_scratch + OFF_CACTS + (size_t)layer * 128 * T_LEN;
        const float* wd   = w_dil_all + (size_t)layer * 16384;

        // stage x (two tap windows)
        for (int idx = tid; idx < 64 * TB; idx += 256) {
            int j = idx / TB, tt = idx % TB;
            int ta = t0 - d + tt;
            XS0[idx] = (ta >= 0) ? xin[(size_t)j * T_LEN + ta] : 0.0f;
            XS1[idx] = xin[(size_t)j * T_LEN + t0 + tt];
        }

        float a4[4] = {0.0f, 0.0f, 0.0f, 0.0f};
        for (int jc = 0; jc < 64; jc += 16) {
            __syncthreads();
            for (int idx = tid; idx < 4096; idx += 256) {
                int cc = idx >> 5, inner = idx & 31;
                WD[inner * 128 + cc] = wd[cc * 128 + jc * 2 + inner];
            }
            __syncthreads();
#pragma unroll
            for (int jj = 0; jj < 16; jj++) {
                float w0 = WD[(2 * jj) * 128 + c];
                float w1 = WD[(2 * jj + 1) * 128 + c];
                int j = jc + jj;
#pragma unroll
                for (int i = 0; i < 4; i++) {
                    int tt = th * 4 + i;
                    a4[i] += w0 * XS0[j * TB + tt] + w1 * XS1[j * TB + tt];
                }
            }
        }

        {
            float bd = b_dil_all[layer * 128 + c];
#pragma unroll
            for (int i = 0; i < 4; i++) {
                int t = t0 + th * 4 + i;
                a4[i] += bd + cond[(size_t)c * T_LEN + t];
            }
        }
        __syncthreads();
        if (c >= 64) {
#pragma unroll
            for (int i = 0; i < 4; i++) IA[(c - 64) * TB + th * 4 + i] = a4[i];
        }
        __syncthreads();
        if (c < 64) {
#pragma unroll
            for (int i = 0; i < 4; i++) {
                int tt = th * 4 + i;
                float g = IA[c * TB + tt];
                float sg = 1.0f / (1.0f + expf(-g));
                ACT[c * TB + tt] = tanhf(a4[i]) * sg;
            }
        }
        __syncthreads();

        // residual
        if (layer < 15) {
            const float* wr = g_scratch + OFF_WRST + (size_t)layer * 4096;
            int c2 = tid & 63, qq = tid >> 6;   // 4 quarters x 2 t
            float r2[2] = {0.0f, 0.0f};
            for (int k = 0; k < 64; k++) {
                float w = wr[k * 64 + c2];
#pragma unroll
                for (int i = 0; i < 2; i++)
                    r2[i] += w * ACT[k * TB + qq * 2 + i];
            }
            float br = b_res_all[layer * 64 + c2];
#pragma unroll
            for (int i = 0; i < 2; i++) {
                int t = t0 + qq * 2 + i;
                xout[(size_t)c2 * T_LEN + t] = xin[(size_t)c2 * T_LEN + t] + r2[i] + br;
            }
        }

        // skip (register accumulator, row = tid)
        {
            const float* wsk = g_scratch + OFF_WSKT + (size_t)layer * 16384;
            for (int k = 0; k < 64; k++) {
                float w = wsk[k * 256 + tid];
                float4 a0 = *reinterpret_cast<const float4*>(&ACT[k * TB]);
                float4 a1 = *reinterpret_cast<const float4*>(&ACT[k * TB + 4]);
                s_acc[0] += w * a0.x; s_acc[1] += w * a0.y;
                s_acc[2] += w * a0.z; s_acc[3] += w * a0.w;
                s_acc[4] += w * a1.x; s_acc[5] += w * a1.y;
                s_acc[6] += w * a1.z; s_acc[7] += w * a1.w;
            }
            float bs = b_skip_all[layer * 256 + tid];
#pragma unroll
            for (int tt = 0; tt < TB; tt++) s_acc[tt] += bs;
        }

        if (layer < 15) gbar();
    }

    // ---- heads (block-local; skip lives in registers) ----
    {
        __syncthreads();
#pragma unroll
        for (int tt = 0; tt < TB; tt++) HS[tid * TB + tt] = fmaxf(s_acc[tt], 0.0f);
        __syncthreads();

        const float* wo = g_scratch + OFF_WOT;
        float h[TB];
#pragma unroll
        for (int tt = 0; tt < TB; tt++) h[tt] = 0.0f;
        for (int cc = 0; cc < 256; cc++) {
            float w = wo[cc * 256 + tid];
            float4 v0 = *reinterpret_cast<const float4*>(&HS[cc * TB]);
            float4 v1 = *reinterpret_cast<const float4*>(&HS[cc * TB + 4]);
            h[0] += w * v0.x; h[1] += w * v0.y; h[2] += w * v0.z; h[3] += w * v0.w;
            h[4] += w * v1.x; h[5] += w * v1.y; h[6] += w * v1.z; h[7] += w * v1.w;
        }
#pragma unroll
        for (int tt = 0; tt < TB; tt++) HS2[tid * TB + tt] = fmaxf(h[tt], 0.0f);
        __syncthreads();

        const float* we = g_scratch + OFF_WET;
        float h2[TB];
#pragma unroll
        for (int tt = 0; tt < TB; tt++) h2[tt] = 0.0f;
        for (int cc = 0; cc < 256; cc++) {
            float w = we[cc * 256 + tid];
            float4 v0 = *reinterpret_cast<const float4*>(&HS2[cc * TB]);
            float4 v1 = *reinterpret_cast<const float4*>(&HS2[cc * TB + 4]);
            h2[0] += w * v0.x; h2[1] += w * v0.y; h2[2] += w * v0.z; h2[3] += w * v0.w;
            h2[4] += w * v1.x; h2[5] += w * v1.y; h2[6] += w * v1.z; h2[7] += w * v1.w;
        }

        if (blockIdx.x == 0) out[(size_t)tid * T_LEN] = 0.0f;
#pragma unroll
        for (int tt = 0; tt < TB; tt++) {
            int t = t0 + tt;
            if (t + 1 < T_LEN) out[(size_t)tid * T_LEN + t + 1] = h2[tt];
        }
    }
}

// ---------------- launch -------------------------------------------------------------
extern "C" void kernel_launch(void* const* d_in, const int* in_sizes, int n_in,
                              void* d_out, int out_size)
{
    const float* features = (const float*)d_in[0];
    const float* audio    = (const float*)d_in[1];
    const float* w_up     = (const float*)d_in[2];
    const float* b_up     = (const float*)d_in[3];
    const float* w_cond   = (const float*)d_in[4];
    const float* b_cond   = (const float*)d_in[5];
    const float* embed    = (const float*)d_in[6];
    const float* w_dil    = (const float*)d_in[7];
    const float* b_dil    = (const float*)d_in[8];
    const float* w_res    = (const float*)d_in[9];
    const float* b_res    = (const float*)d_in[10];
    const float* w_skip   = (const float*)d_in[11];
    const float* b_skip   = (const float*)d_in[12];
    const float* w_out    = (const float*)d_in[13];
    const float* w_end    = (const float*)d_in[14];
    float* out = (float*)d_out;

    float* scr = nullptr;
    cudaGetSymbolAddress((void**)&scr, g_scratch);

    __nv_bfloat16* WC_HI = (__nv_bfloat16*)(scr + OFF_WC_HI);
    __nv_bfloat16* WC_LO = (__nv_bfloat16*)(scr + OFF_WC_LO);
    __nv_bfloat16* FT_HI = (__nv_bfloat16*)(scr + OFF_FT_HI);
    __nv_bfloat16* FT_LO = (__nv_bfloat16*)(scr + OFF_FT_LO);
    __nv_bfloat16* BR_HI = (__nv_bfloat16*)(scr + OFF_BR_HI);
    __nv_bfloat16* BR_LO = (__nv_bfloat16*)(scr + OFF_BR_LO);
    __nv_bfloat16* B2_HI = (__nv_bfloat16*)(scr + OFF_B2_HI);
    __nv_bfloat16* B2_LO = (__nv_bfloat16*)(scr + OFF_B2_LO);

    cudaFuncSetAttribute(k_gemm_tc, cudaFuncAttributeMaxDynamicSharedMemorySize, 67584);

    int write_q = (out_size >= 256 * T_LEN + T_LEN) ? 1 : 0;

    dim3 tb(32, 8);
    // [1..5]
    k_tsplit<<<dim3(4, 64), tb>>>(features, FT_HI, FT_LO, 2048, 128);
    k_split<<<(2048 * 2048) / 256, 256>>>(w_cond, WC_HI, WC_LO, 2048 * 2048);
    k_transpose_b<<<dim3(2, 8, 16), tb>>>(w_skip, scr + OFF_WSKT, 256, 64,
                                          256 * 64, 64 * 256);
    k_transpose_b<<<dim3(2, 2, 15), tb>>>(w_res, scr + OFF_WRST, 64, 64,
                                          64 * 64, 64 * 64);
    k_transpose<<<dim3(8, 8), tb>>>(w_out, scr + OFF_WOT, 256, 256);

    // [6] upsample GEMM (profiled by ncu -s 5 -c 1)
    k_gemm_tc<<<dim3(256, 1), 256, 67584>>>(nullptr, nullptr, w_up, 32768, 1,
                                            FT_HI, FT_LO, 2048, 0,
                                            b_up, nullptr, BR_HI, BR_LO);
    k_transpose<<<dim3(8, 8), tb>>>(w_end, scr + OFF_WET, 256, 256);
    // cond GEMM #1 -> cond1^T hi/lo
    k_gemm_tc<<<dim3(16, 8), 256, 67584>>>(WC_HI, WC_LO, nullptr, 0, 0,
                                           BR_HI, BR_LO, 2048, 1,
                                           b_cond, nullptr, B2_HI, B2_LO);
    // cond GEMM #2 -> cond_acts fp32 [2048][1016]
    k_gemm_tc<<<dim3(16, 8), 256, 67584>>>(WC_HI, WC_LO, nullptr, 0, 0,
                                           B2_HI, B2_LO, 2048, 2,
                                           b_cond, scr + OFF_CACTS, nullptr, nullptr);

    // fused persistent tail
    k_reset<<<1, 1>>>();
    k_tail<<<NBLK, 256>>>(audio, embed, w_dil, b_dil, b_res, b_skip, out, write_q);
}

// round 6
// speedup vs baseline: 2.5765x; 1.1380x over previous
#include <cuda_runtime.h>
#include <cuda_bf16.h>
#include <math.h>
#include <stdint.h>

#define T_LEN 1016
#define TB 8
#define NBLK 127

// ---------------- scratch layout (float units) -------------------------------------
constexpr size_t OFF_WC_HI  = 0;
constexpr size_t OFF_WC_LO  = OFF_WC_HI  + 2097152;
constexpr size_t OFF_FT_HI  = OFF_WC_LO  + 2097152;
constexpr size_t OFF_FT_LO  = OFF_FT_HI  + 131072;
constexpr size_t OFF_BR_HI  = OFF_FT_LO  + 131072;
constexpr size_t OFF_BR_LO  = OFF_BR_HI  + 1048576;
constexpr size_t OFF_B2_HI  = OFF_BR_LO  + 1048576;
constexpr size_t OFF_B2_LO  = OFF_B2_HI  + 1048576;
constexpr size_t OFF_CACTS  = OFF_B2_LO  + 1048576;
constexpr size_t OFF_WOT    = OFF_CACTS  + 2080768;
constexpr size_t OFF_WET    = OFF_WOT    + 65536;
constexpr size_t OFF_X0     = OFF_WET    + 65536;
constexpr size_t OFF_X1     = OFF_X0     + 65024;
constexpr size_t OFF_Q      = OFF_X1     + 65024;
constexpr size_t OFF_WSKT   = OFF_Q      + 1024;
constexpr size_t OFF_WRST   = OFF_WSKT   + 262144;
constexpr size_t SCRATCH_SZ = OFF_WRST + 61440;

__device__ __align__(1024) float g_scratch[SCRATCH_SZ];
__device__ unsigned g_bar;

// ---------------- PTX helpers -------------------------------------------------------
__device__ __forceinline__ uint32_t s2u(const void* p) {
    uint32_t a;
    asm("{ .reg .u64 t; cvta.to.shared.u64 t, %1; cvt.u32.u64 %0, t; }" : "=r"(a) : "l"(p));
    return a;
}
__device__ __forceinline__ void cp16(uint32_t dst, const void* src) {
    asm volatile("cp.async.cg.shared.global [%0], [%1], 16;" :: "r"(dst), "l"(src));
}
#define CP_COMMIT() asm volatile("cp.async.commit_group;" ::: "memory")

__device__ __forceinline__ void ldsm4(uint32_t* r, uint32_t a) {
    asm volatile("ldmatrix.sync.aligned.m8n8.x4.shared.b16 {%0,%1,%2,%3}, [%4];"
                 : "=r"(r[0]), "=r"(r[1]), "=r"(r[2]), "=r"(r[3]) : "r"(a));
}
__device__ __forceinline__ void ldsm4t(uint32_t* r, uint32_t a) {
    asm volatile("ldmatrix.sync.aligned.m8n8.x4.trans.shared.b16 {%0,%1,%2,%3}, [%4];"
                 : "=r"(r[0]), "=r"(r[1]), "=r"(r[2]), "=r"(r[3]) : "r"(a));
}
__device__ __forceinline__ void mma_bf16(float* c, const uint32_t* a, const uint32_t* b) {
    asm volatile("mma.sync.aligned.m16n8k16.row.col.f32.bf16.bf16.f32 "
                 "{%0,%1,%2,%3}, {%4,%5,%6,%7}, {%8,%9}, {%0,%1,%2,%3};"
                 : "+f"(c[0]), "+f"(c[1]), "+f"(c[2]), "+f"(c[3])
                 : "r"(a[0]), "r"(a[1]), "r"(a[2]), "r"(a[3]), "r"(b[0]), "r"(b[1]));
}

__device__ __forceinline__ uint32_t off_km(int row, int kk) {
    return (uint32_t)(row * 64 + ((kk ^ ((row >> 1) & 3)) << 4));
}
__device__ __forceinline__ uint32_t off_tr(int k, int mc) {
    return (uint32_t)(k * 256 + ((mc ^ (k & 7)) << 4));
}
__device__ __forceinline__ uint32_t bpack(float x, float y) {
    uint32_t lo = (uint32_t)__bfloat16_as_ushort(__float2bfloat16(x));
    uint32_t hi = (uint32_t)__bfloat16_as_ushort(__float2bfloat16(y));
    return lo | (hi << 16);
}

// ---------------- transposes / splits ------------------------------------------------
__global__ void k_transpose(const float* __restrict__ in, float* __restrict__ out,
                            int R, int C)
{
    __shared__ float tile[32][33];
    int c0 = blockIdx.x * 32, r0 = blockIdx.y * 32;
    int x = threadIdx.x, y = threadIdx.y;
#pragma unroll
    for (int i = 0; i < 32; i += 8)
        tile[y + i][x] = in[(size_t)(r0 + y + i) * C + c0 + x];
    __syncthreads();
#pragma unroll
    for (int i = 0; i < 32; i += 8)
        out[(size_t)(c0 + y + i) * R + r0 + x] = tile[x][y + i];
}

__global__ void k_transpose_b(const float* __restrict__ in, float* __restrict__ out,
                              int R, int C, size_t inL, size_t outL)
{
    __shared__ float tile[32][33];
    int l = blockIdx.z;
    const float* ip = in + (size_t)l * inL;
    float* op = out + (size_t)l * outL;
    int c0 = blockIdx.x * 32, r0 = blockIdx.y * 32;
    int x = threadIdx.x, y = threadIdx.y;
#pragma unroll
    for (int i = 0; i < 32; i += 8)
        tile[y + i][x] = ip[(size_t)(r0 + y + i) * C + c0 + x];
    __syncthreads();
#pragma unroll
    for (int i = 0; i < 32; i += 8)
        op[(size_t)(c0 + y + i) * R + r0 + x] = tile[x][y + i];
}

__global__ void k_tsplit(const float* __restrict__ in, __nv_bfloat16* __restrict__ hi,
                         __nv_bfloat16* __restrict__ lo, int R, int C)
{
    __shared__ float tile[32][33];
    int c0 = blockIdx.x * 32, r0 = blockIdx.y * 32;
    int x = threadIdx.x, y = threadIdx.y;
#pragma unroll
    for (int i = 0; i < 32; i += 8)
        tile[y + i][x] = in[(size_t)(r0 + y + i) * C + c0 + x];
    __syncthreads();
#pragma unroll
    for (int i = 0; i < 32; i += 8) {
        float v = tile[x][y + i];
        size_t o = (size_t)(c0 + y + i) * R + r0 + x;
        __nv_bfloat16 h = __float2bfloat16(v);
        hi[o] = h;
        lo[o] = __float2bfloat16(v - __bfloat162float(h));
    }
}

__global__ void k_split4(const float* __restrict__ in, __nv_bfloat16* __restrict__ hi,
                         __nv_bfloat16* __restrict__ lo, int n4)
{
    int i = blockIdx.x * 256 + threadIdx.x;
    if (i >= n4) return;
    float4 v = reinterpret_cast<const float4*>(in)[i];
    __nv_bfloat16 h0 = __float2bfloat16(v.x), h1 = __float2bfloat16(v.y);
    __nv_bfloat16 h2 = __float2bfloat16(v.z), h3 = __float2bfloat16(v.w);
    uint2 vh = make_uint2(
        (uint32_t)__bfloat16_as_ushort(h0) | ((uint32_t)__bfloat16_as_ushort(h1) << 16),
        (uint32_t)__bfloat16_as_ushort(h2) | ((uint32_t)__bfloat16_as_ushort(h3) << 16));
    uint2 vl = make_uint2(bpack(v.x - __bfloat162float(h0), v.y - __bfloat162float(h1)),
                          bpack(v.z - __bfloat162float(h2), v.w - __bfloat162float(h3)));
    reinterpret_cast<uint2*>(hi)[i] = vh;
    reinterpret_cast<uint2*>(lo)[i] = vl;
}

// ---------------- mma.sync split-bf16 GEMM, 512 thr, 3-stage pipeline ---------------
__global__ __launch_bounds__(512)
void k_gemm_tc(const __nv_bfloat16* __restrict__ Ahi, const __nv_bfloat16* __restrict__ Alo,
               const float* __restrict__ Af32, int Mg, int afp32,
               const __nv_bfloat16* __restrict__ Bhi, const __nv_bfloat16* __restrict__ Blo,
               int K, int mode, const float* __restrict__ bias,
               float* __restrict__ outF,
               __nv_bfloat16* __restrict__ outHi, __nv_bfloat16* __restrict__ outLo)
{
    extern __shared__ char smem[];
    uint32_t sb = s2u(smem);
    const int tid = threadIdx.x;
    const int wid = tid >> 5, lane = tid & 31;
    const int bm = blockIdx.x * 128, bn = blockIdx.y * 128;
    const int wm = (wid & 3) * 32, wn = (wid >> 2) * 32;
    const uint32_t STG = 32768;   // A_HI 0 | A_LO 8192 | B_HI 16384 | B_LO 24576

    float acc[2][4][4];
#pragma unroll
    for (int mt = 0; mt < 2; mt++)
#pragma unroll
        for (int nt = 0; nt < 4; nt++)
#pragma unroll
            for (int i = 0; i < 4; i++) acc[mt][nt][i] = 0.0f;

    const int nsteps = K >> 5;
    const int row = tid >> 2, kk = tid & 3;     // one 16B chunk per tensor per thread
    const uint32_t dkm = off_km(row, kk);
    float4 pre[2];

    auto ldg_pre = [&](int k0) {
#pragma unroll
        for (int i = 0; i < 2; i++) {
            int u = tid + i * 512;
            int k = u >> 5, f4 = u & 31;
            pre[i] = *reinterpret_cast<const float4*>(Af32 + (size_t)(k0 + k) * Mg + bm + f4 * 4);
        }
    };
    auto sts_pre = [&](int s) {
#pragma unroll
        for (int i = 0; i < 2; i++) {
            int u = tid + i * 512;
            int k = u >> 5, f4 = u & 31;
            float4 v = pre[i];
            __nv_bfloat16 h0 = __float2bfloat16(v.x), h1 = __float2bfloat16(v.y);
            __nv_bfloat16 h2 = __float2bfloat16(v.z), h3 = __float2bfloat16(v.w);
            uint32_t hi01 = (uint32_t)__bfloat16_as_ushort(h0) |
                            ((uint32_t)__bfloat16_as_ushort(h1) << 16);
            uint32_t hi23 = (uint32_t)__bfloat16_as_ushort(h2) |
                            ((uint32_t)__bfloat16_as_ushort(h3) << 16);
            uint32_t lo01 = bpack(v.x - __bfloat162float(h0), v.y - __bfloat162float(h1));
            uint32_t lo23 = bpack(v.z - __bfloat162float(h2), v.w - __bfloat162float(h3));
            int mc = f4 >> 1, half = f4 & 1;
            uint32_t a = (uint32_t)s * STG + off_tr(k, mc) + half * 8;
            *reinterpret_cast<uint2*>(smem + a) = make_uint2(hi01, hi23);
            *reinterpret_cast<uint2*>(smem + 8192 + a) = make_uint2(lo01, lo23);
        }
    };
    auto fill_b = [&](int s, int k0) {
        uint32_t base = sb + (uint32_t)s * STG;
        cp16(base + 16384 + dkm, Bhi + (size_t)(bn + row) * K + k0 + kk * 8);
        cp16(base + 24576 + dkm, Blo + (size_t)(bn + row) * K + k0 + kk * 8);
    };
    auto fill_a = [&](int s, int k0) {
        uint32_t base = sb + (uint32_t)s * STG;
        cp16(base + dkm,        Ahi + (size_t)(bm + row) * K + k0 + kk * 8);
        cp16(base + 8192 + dkm, Alo + (size_t)(bm + row) * K + k0 + kk * 8);
    };

    // ---- prologue: stages 0 and 1 ----
    if (afp32) {
        ldg_pre(0);
        sts_pre(0);
        ldg_pre(32);
        fill_b(0, 0);  CP_COMMIT();
        fill_b(1, 32); CP_COMMIT();
    } else {
        fill_a(0, 0);  fill_b(0, 0);  CP_COMMIT();
        fill_a(1, 32); fill_b(1, 32); CP_COMMIT();
    }

    int sc = 0;
    for (int it = 0; it < nsteps; it++) {
        int sn = sc + 1; if (sn == 3) sn = 0;
        int sf = sn + 1; if (sf == 3) sf = 0;

        if (it < nsteps - 1)
            asm volatile("cp.async.wait_group 1;" ::: "memory");
        else
            asm volatile("cp.async.wait_group 0;" ::: "memory");
        __syncthreads();

        if (afp32) {
            if (it + 1 < nsteps) sts_pre(sn);
            if (it + 2 < nsteps) {
                ldg_pre((it + 2) * 32);
                fill_b(sf, (it + 2) * 32);
                CP_COMMIT();
            }
        } else if (it + 2 < nsteps) {
            fill_a(sf, (it + 2) * 32);
            fill_b(sf, (it + 2) * 32);
            CP_COMMIT();
        }

        // ---- compute stage sc ----
        uint32_t base = sb + (uint32_t)sc * STG;
#pragma unroll
        for (int s = 0; s < 2; s++) {
            const int kk0 = s * 2;
            uint32_t af[2][2][4];
#pragma unroll
            for (int mt = 0; mt < 2; mt++) {
                if (afp32) {
                    int k  = s * 16 + ((lane >> 4) << 3) + (lane & 7);
                    int mc = ((wm + mt * 16) >> 3) + ((lane >> 3) & 1);
                    uint32_t ad = off_tr(k, mc);
                    ldsm4t(af[mt][0], base + ad);
                    ldsm4t(af[mt][1], base + 8192 + ad);
                } else {
                    int r2 = wm + mt * 16 + (lane & 15);
                    int k2 = kk0 + (lane >> 4);
                    uint32_t ad = off_km(r2, k2);
                    ldsm4(af[mt][0], base + ad);
                    ldsm4(af[mt][1], base + 8192 + ad);
                }
            }
            uint32_t bh[4][2], bl[4][2];
#pragma unroll
            for (int p = 0; p < 2; p++) {
                int r2 = wn + p * 16 + ((lane >> 4) << 3) + (lane & 7);
                int k2 = kk0 + ((lane >> 3) & 1);
                uint32_t bd = off_km(r2, k2);
                uint32_t r[4];
                ldsm4(r, base + 16384 + bd);
                bh[2 * p][0] = r[0]; bh[2 * p][1] = r[1];
                bh[2 * p + 1][0] = r[2]; bh[2 * p + 1][1] = r[3];
                ldsm4(r, base + 24576 + bd);
                bl[2 * p][0] = r[0]; bl[2 * p][1] = r[1];
                bl[2 * p + 1][0] = r[2]; bl[2 * p + 1][1] = r[3];
            }
#pragma unroll
            for (int mt = 0; mt < 2; mt++)
#pragma unroll
                for (int nt = 0; nt < 4; nt++) {
                    mma_bf16(acc[mt][nt], af[mt][0], bh[nt]);
                    mma_bf16(acc[mt][nt], af[mt][0], bl[nt]);
                    mma_bf16(acc[mt][nt], af[mt][1], bh[nt]);
                }
        }
        sc = sn;
    }
    __syncthreads();

    // ---- stage D (128x128) to smem, stride 129 ----
    float* sd = reinterpret_cast<float*>(smem);
#pragma unroll
    for (int mt = 0; mt < 2; mt++)
#pragma unroll
        for (int nt = 0; nt < 4; nt++) {
            int r = wm + mt * 16 + (lane >> 2);
            int c = wn + nt * 8 + (lane & 3) * 2;
            sd[r * 129 + c]           = acc[mt][nt][0];
            sd[r * 129 + c + 1]       = acc[mt][nt][1];
            sd[(r + 8) * 129 + c]     = acc[mt][nt][2];
            sd[(r + 8) * 129 + c + 1] = acc[mt][nt][3];
        }
    __syncthreads();

    if (mode == 0) {
        int bo = bm >> 4;
        for (int u = tid; u < T_LEN; u += 512) {
            int m = u >> 3, p = u & 7;
            uint4 vh, vl;
            __nv_bfloat16* hp = (__nv_bfloat16*)&vh;
            __nv_bfloat16* lp = (__nv_bfloat16*)&vl;
#pragma unroll
            for (int ol = 0; ol < 8; ol++) {
                float v = sd[(ol * 16 + p + 8) * 129 + m] +
                          sd[(ol * 16 + p) * 129 + m + 1] + bias[bo + ol];
                __nv_bfloat16 h = __float2bfloat16(v);
                hp[ol] = h;
                lp[ol] = __float2bfloat16(v - __bfloat162float(h));
            }
            *reinterpret_cast<uint4*>(outHi + (size_t)u * 2048 + bo) = vh;
            *reinterpret_cast<uint4*>(outLo + (size_t)u * 2048 + bo) = vl;
        }
    } else if (mode == 1) {
        int mg = (tid & 31) * 4;
        int nl = tid >> 5;
        for (int n0 = 0; n0 < 128; n0 += 16) {
            int n = n0 + nl;
            uint2 vh, vl;
            __nv_bfloat16* hp = (__nv_bfloat16*)&vh;
            __nv_bfloat16* lp = (__nv_bfloat16*)&vl;
#pragma unroll
            for (int j = 0; j < 4; j++) {
                float v = sd[(mg + j) * 129 + n] + bias[bm + mg + j];
                __nv_bfloat16 h = __float2bfloat16(v);
                hp[j] = h;
                lp[j] = __float2bfloat16(v - __bfloat162float(h));
            }
            *reinterpret_cast<uint2*>(outHi + (size_t)(bn + n) * 2048 + bm + mg) = vh;
            *reinterpret_cast<uint2*>(outLo + (size_t)(bn + n) * 2048 + bm + mg) = vl;
        }
    } else {
        int mo = tid >> 7, n = tid & 127;
        int gn = bn + n;
        if (gn < T_LEN) {
            for (int m0 = 0; m0 < 128; m0 += 4) {
                int m = m0 + mo;
                outF[(size_t)(bm + m) * T_LEN + gn] = sd[m * 129 + n] + bias[bm + m];
            }
        }
    }
}

// ---------------- barrier reset ------------------------------------------------------
__global__ void k_reset() { g_bar = 0; }

// ---------------- fused persistent tail ---------------------------------------------
__global__ __launch_bounds__(256)
void k_tail(const float* __restrict__ audio, const float* __restrict__ embed,
            const float* __restrict__ w_dil_all, const float* __restrict__ b_dil_all,
            const float* __restrict__ b_res_all, const float* __restrict__ b_skip_all,
            float* __restrict__ out, int write_q)
{
    __shared__ float WD[4096];
    __shared__ float XS0[64 * TB];
    __shared__ float XS1[64 * TB];
    __shared__ float IA[64 * TB];
    __shared__ float ACT[64 * TB];
    __shared__ float HS[256 * TB];
    __shared__ float HS2[256 * TB];
    __shared__ int QS[TB];

    const int tid = threadIdx.x;
    const int t0 = blockIdx.x * TB;
    unsigned bar_target = 0;

    if (tid < TB) {
        int t = t0 + tid;
        float x = audio[t];
        float xc = fminf(1.0f, fmaxf(-1.0f, x));
        float s  = (xc > 0.0f) ? 1.0f : ((xc < 0.0f) ? -1.0f : 0.0f);
        float num = log1pf(__fmul_rn(255.0f, fabsf(xc)));
        float den = log1pf(255.0f);
        float m = __fdiv_rn(__fmul_rn(s, num), den);
        float v = __fadd_rn(__fmul_rn(__fmul_rn(__fadd_rn(m, 1.0f), 0.5f), 255.0f), 0.5f);
        v = fminf(255.0f, fmaxf(0.0f, v));
        int q = (int)v;
        QS[tid] = q;
        if (write_q) out[(size_t)256 * T_LEN + t] = (float)q;
    }
    __syncthreads();

    {
        float* X0 = g_scratch + OFF_X0;
        for (int idx = tid; idx < 64 * TB; idx += 256) {
            int j = idx / TB, tt = idx % TB;
            X0[(size_t)j * T_LEN + t0 + tt] = embed[QS[tt] * 64 + j];
        }
    }

    auto gbar = [&]() {
        bar_target += NBLK;
        __syncthreads();
        __threadfence();
        if (tid == 0) {
            atomicAdd(&g_bar, 1u);
            unsigned v;
            do {
                asm volatile("ld.global.acquire.gpu.u32 %0, [%1];"
                             : "=r"(v) : "l"(&g_bar) : "memory");
            } while (v < bar_target);
        }
        __syncthreads();
    };
    gbar();

    float s_acc[TB];
#pragma unroll
    for (int tt = 0; tt < TB; tt++) s_acc[tt] = 0.0f;

    const int c  = tid & 127;
    const int th = tid >> 7;

    for (int layer = 0; layer < 16; layer++) {
        const int d = 1 << (layer & 7);
        const float* xin  = g_scratch + ((layer & 1) ? OFF_X1 : OFF_X0);
        float*       xout = g_scratch + ((layer & 1) ? OFF_X0 : OFF_X1);
        const float* cond = g_scratch + OFF_CACTS + (size_t)layer * 128 * T_LEN;
        const float* wd   = w_dil_all + (size_t)layer * 16384;

        for (int idx = tid; idx < 64 * TB; idx += 256) {
            int j = idx / TB, tt = idx % TB;
            int ta = t0 - d + tt;
            XS0[idx] = (ta >= 0) ? xin[(size_t)j * T_LEN + ta] : 0.0f;
            XS1[idx] = xin[(size_t)j * T_LEN + t0 + tt];
        }

        float a4[4] = {0.0f, 0.0f, 0.0f, 0.0f};
        for (int jc = 0; jc < 64; jc += 16) {
            __syncthreads();
            for (int idx = tid; idx < 4096; idx += 256) {
                int cc = idx >> 5, inner = idx & 31;
                WD[inner * 128 + cc] = wd[cc * 128 + jc * 2 + inner];
            }
            __syncthreads();
#pragma unroll
            for (int jj = 0; jj < 16; jj++) {
                float w0 = WD[(2 * jj) * 128 + c];
                float w1 = WD[(2 * jj + 1) * 128 + c];
                int j = jc + jj;
#pragma unroll
                for (int i = 0; i < 4; i++) {
                    int tt = th * 4 + i;
                    a4[i] += w0 * XS0[j * TB + tt] + w1 * XS1[j * TB + tt];
                }
            }
        }

        {
            float bd = b_dil_all[layer * 128 + c];
#pragma unroll
            for (int i = 0; i < 4; i++) {
                int t = t0 + th * 4 + i;
                a4[i] += bd + cond[(size_t)c * T_LEN + t];
            }
        }
        __syncthreads();
        if (c >= 64) {
#pragma unroll
            for (int i = 0; i < 4; i++) IA[(c - 64) * TB + th * 4 + i] = a4[i];
        }
        __syncthreads();
        if (c < 64) {
#pragma unroll
            for (int i = 0; i < 4; i++) {
                int tt = th * 4 + i;
                float g = IA[c * TB + tt];
                float sg = 1.0f / (1.0f + expf(-g));
                ACT[c * TB + tt] = tanhf(a4[i]) * sg;
            }
        }
        __syncthreads();

        if (layer < 15) {
            const float* wr = g_scratch + OFF_WRST + (size_t)layer * 4096;
            int c2 = tid & 63, qq = tid >> 6;
            float r2[2] = {0.0f, 0.0f};
            for (int k = 0; k < 64; k++) {
                float w = wr[k * 64 + c2];
#pragma unroll
                for (int i = 0; i < 2; i++)
                    r2[i] += w * ACT[k * TB + qq * 2 + i];
            }
            float br = b_res_all[layer * 64 + c2];
#pragma unroll
            for (int i = 0; i < 2; i++) {
                int t = t0 + qq * 2 + i;
                xout[(size_t)c2 * T_LEN + t] = xin[(size_t)c2 * T_LEN + t] + r2[i] + br;
            }
        }

        {
            const float* wsk = g_scratch + OFF_WSKT + (size_t)layer * 16384;
            for (int k = 0; k < 64; k++) {
                float w = wsk[k * 256 + tid];
                float4 a0 = *reinterpret_cast<const float4*>(&ACT[k * TB]);
                float4 a1 = *reinterpret_cast<const float4*>(&ACT[k * TB + 4]);
                s_acc[0] += w * a0.x; s_acc[1] += w * a0.y;
                s_acc[2] += w * a0.z; s_acc[3] += w * a0.w;
                s_acc[4] += w * a1.x; s_acc[5] += w * a1.y;
                s_acc[6] += w * a1.z; s_acc[7] += w * a1.w;
            }
            float bs = b_skip_all[layer * 256 + tid];
#pragma unroll
            for (int tt = 0; tt < TB; tt++) s_acc[tt] += bs;
        }

        if (layer < 15) gbar();
    }

    {
        __syncthreads();
#pragma unroll
        for (int tt = 0; tt < TB; tt++) HS[tid * TB + tt] = fmaxf(s_acc[tt], 0.0f);
        __syncthreads();

        const float* wo = g_scratch + OFF_WOT;
        float h[TB];
#pragma unroll
        for (int tt = 0; tt < TB; tt++) h[tt] = 0.0f;
        for (int cc = 0; cc < 256; cc++) {
            float w = wo[cc * 256 + tid];
            float4 v0 = *reinterpret_cast<const float4*>(&HS[cc * TB]);
            float4 v1 = *reinterpret_cast<const float4*>(&HS[cc * TB + 4]);
            h[0] += w * v0.x; h[1] += w * v0.y; h[2] += w * v0.z; h[3] += w * v0.w;
            h[4] += w * v1.x; h[5] += w * v1.y; h[6] += w * v1.z; h[7] += w * v1.w;
        }
#pragma unroll
        for (int tt = 0; tt < TB; tt++) HS2[tid * TB + tt] = fmaxf(h[tt], 0.0f);
        __syncthreads();

        const float* we = g_scratch + OFF_WET;
        float h2[TB];
#pragma unroll
        for (int tt = 0; tt < TB; tt++) h2[tt] = 0.0f;
        for (int cc = 0; cc < 256; cc++) {
            float w = we[cc * 256 + tid];
            float4 v0 = *reinterpret_cast<const float4*>(&HS2[cc * TB]);
            float4 v1 = *reinterpret_cast<const float4*>(&HS2[cc * TB + 4]);
            h2[0] += w * v0.x; h2[1] += w * v0.y; h2[2] += w * v0.z; h2[3] += w * v0.w;
            h2[4] += w * v1.x; h2[5] += w * v1.y; h2[6] += w * v1.z; h2[7] += w * v1.w;
        }

        if (blockIdx.x == 0) out[(size_t)tid * T_LEN] = 0.0f;
#pragma unroll
        for (int tt = 0; tt < TB; tt++) {
            int t = t0 + tt;
            if (t + 1 < T_LEN) out[(size_t)tid * T_LEN + t + 1] = h2[tt];
        }
    }
}

// ---------------- launch -------------------------------------------------------------
extern "C" void kernel_launch(void* const* d_in, const int* in_sizes, int n_in,
                              void* d_out, int out_size)
{
    const float* features = (const float*)d_in[0];
    const float* audio    = (const float*)d_in[1];
    const float* w_up     = (const float*)d_in[2];
    const float* b_up     = (const float*)d_in[3];
    const float* w_cond   = (const float*)d_in[4];
    const float* b_cond   = (const float*)d_in[5];
    const float* embed    = (const float*)d_in[6];
    const float* w_dil    = (const float*)d_in[7];
    const float* b_dil    = (const float*)d_in[8];
    const float* w_res    = (const float*)d_in[9];
    const float* b_res    = (const float*)d_in[10];
    const float* w_skip   = (const float*)d_in[11];
    const float* b_skip   = (const float*)d_in[12];
    const float* w_out    = (const float*)d_in[13];
    const float* w_end    = (const float*)d_in[14];
    float* out = (float*)d_out;

    float* scr = nullptr;
    cudaGetSymbolAddress((void**)&scr, g_scratch);

    __nv_bfloat16* WC_HI = (__nv_bfloat16*)(scr + OFF_WC_HI);
    __nv_bfloat16* WC_LO = (__nv_bfloat16*)(scr + OFF_WC_LO);
    __nv_bfloat16* FT_HI = (__nv_bfloat16*)(scr + OFF_FT_HI);
    __nv_bfloat16* FT_LO = (__nv_bfloat16*)(scr + OFF_FT_LO);
    __nv_bfloat16* BR_HI = (__nv_bfloat16*)(scr + OFF_BR_HI);
    __nv_bfloat16* BR_LO = (__nv_bfloat16*)(scr + OFF_BR_LO);
    __nv_bfloat16* B2_HI = (__nv_bfloat16*)(scr + OFF_B2_HI);
    __nv_bfloat16* B2_LO = (__nv_bfloat16*)(scr + OFF_B2_LO);

    cudaFuncSetAttribute(k_gemm_tc, cudaFuncAttributeMaxDynamicSharedMemorySize, 98304);

    int write_q = (out_size >= 256 * T_LEN + T_LEN) ? 1 : 0;

    dim3 tb(32, 8);
    // [1..3]
    k_tsplit<<<dim3(4, 64), tb>>>(features, FT_HI, FT_LO, 2048, 128);
    k_split4<<<(2048 * 2048 / 4 + 255) / 256, 256>>>(w_cond, WC_HI, WC_LO, 2048 * 2048 / 4);
    k_transpose<<<dim3(8, 8), tb>>>(w_out, scr + OFF_WOT, 256, 256);

    // [4] upsample GEMM — target for ncu (-s 5 lands on our 4th launch)
    k_gemm_tc<<<dim3(256, 1), 512, 98304>>>(nullptr, nullptr, w_up, 32768, 1,
                                            FT_HI, FT_LO, 2048, 0,
                                            b_up, nullptr, BR_HI, BR_LO);
    k_transpose<<<dim3(8, 8), tb>>>(w_end, scr + OFF_WET, 256, 256);

    // cond GEMM #1 / #2
    k_gemm_tc<<<dim3(16, 8), 512, 98304>>>(WC_HI, WC_LO, nullptr, 0, 0,
                                           BR_HI, BR_LO, 2048, 1,
                                           b_cond, nullptr, B2_HI, B2_LO);
    k_gemm_tc<<<dim3(16, 8), 512, 98304>>>(WC_HI, WC_LO, nullptr, 0, 0,
                                           B2_HI, B2_LO, 2048, 2,
                                           b_cond, scr + OFF_CACTS, nullptr, nullptr);

    k_transpose_b<<<dim3(2, 8, 16), tb>>>(w_skip, scr + OFF_WSKT, 256, 64,
                                          256 * 64, 64 * 256);
    k_transpose_b<<<dim3(2, 2, 15), tb>>>(w_res, scr + OFF_WRST, 64, 64,
                                          64 * 64, 64 * 64);

    k_reset<<<1, 1>>>();
    k_tail<<<NBLK, 256>>>(audio, embed, w_dil, b_dil, b_res, b_skip, out, write_q);
}